// round 14
// baseline (speedup 1.0000x reference)
#include <cuda_runtime.h>
#include <cuda_bf16.h>
#include <cstdint>
#include <math.h>

#define NQ 128
#define ND 1024
#define DD 256
#define CAT 512
#define EQMAX 2048
#define EDMAX 32768
#define EMMAX 8192

// ---------------- device scratch ----------------
__device__ float g_qh[NQ * DD];
__device__ float g_dh[ND * DD];
__device__ float g_qB[NQ * CAT];
__device__ float g_dB[ND * CAT];
__device__ float g_cosw[EMMAX];
__device__ float g_Bq[NQ * DD];
__device__ float g_Bd[ND * DD];

// CSR structures (static graphs -> built once per run)
__device__ int   g_qoff[NQ + 1],  g_qsrcs[EQMAX];
__device__ float g_qcoef[EQMAX];
__device__ int   g_doff[ND + 1],  g_dsrcs[EDMAX];
__device__ float g_dcoef[EDMAX];
__device__ int   g_mqoff[NQ + 1];
__device__ int2  g_mql[EMMAX];            // (edge, d-node)
__device__ int   g_mdoff[ND + 1];
__device__ int2  g_mdl[EMMAX];            // (edge, q-node)

// packed weights: [N][K] bf16, hi and lo parts
#define OFF_QW0 0
#define OFF_DW0 65536
#define OFF_QW1 131072
#define OFF_DW1 262144
#define OFF_W1T 393216
#define OFF_W1B 655360
#define OFF_W2  917504
#define OFF_W3  1048576
#define WPACK_TOTAL 1081344
__device__ __align__(16) __nv_bfloat16 g_wh[WPACK_TOTAL];
__device__ __align__(16) __nv_bfloat16 g_wl[WPACK_TOTAL];

// ---------------- shared helpers ----------------
__device__ __forceinline__ void mma_bf16(float c[4],
                                         uint32_t a0, uint32_t a1, uint32_t a2, uint32_t a3,
                                         uint32_t b0, uint32_t b1)
{
    asm volatile("mma.sync.aligned.m16n8k16.row.col.f32.bf16.bf16.f32 "
                 "{%0,%1,%2,%3}, {%4,%5,%6,%7}, {%8,%9}, {%0,%1,%2,%3};"
                 : "+f"(c[0]), "+f"(c[1]), "+f"(c[2]), "+f"(c[3])
                 : "r"(a0), "r"(a1), "r"(a2), "r"(a3), "r"(b0), "r"(b1));
}

__device__ __forceinline__ void split_pack(float v0, float v1, uint32_t& hi, uint32_t& lo)
{
    asm("cvt.rn.bf16x2.f32 %0, %1, %2;" : "=r"(hi) : "f"(v1), "f"(v0));
    float h0 = __uint_as_float(hi << 16);
    float h1 = __uint_as_float(hi & 0xffff0000u);
    float r0 = v0 - h0, r1 = v1 - h1;
    asm("cvt.rn.bf16x2.f32 %0, %1, %2;" : "=r"(lo) : "f"(r1), "f"(r0));
}

// ---------------- weight pack: transpose + bf16 split ----------------
struct PackJob { const float* src; int K, N, ld; int64_t off; };
struct PackArgs { PackJob j[8]; };

__global__ void pack_kernel(PackArgs pa, __nv_bfloat16* __restrict__ wh,
                            __nv_bfloat16* __restrict__ wl)
{
    __shared__ float tile[32][33];
    const PackJob jb = pa.j[blockIdx.y];
    int ntilesK = jb.K >> 5;
    int ntiles = ntilesK * (jb.N >> 5);
    if ((int)blockIdx.x >= ntiles) return;
    int kt = blockIdx.x % ntilesK, nt = blockIdx.x / ntilesK;
    int tx = threadIdx.x & 31, ty = threadIdx.x >> 5;
    #pragma unroll
    for (int p = 0; p < 4; p++) {
        int row = ty + p * 8;
        tile[row][tx] = jb.src[(size_t)(kt * 32 + row) * jb.ld + nt * 32 + tx];
    }
    __syncthreads();
    #pragma unroll
    for (int p = 0; p < 4; p++) {
        int row = ty + p * 8;
        float v = tile[tx][row];
        __nv_bfloat16 h = __float2bfloat16(v);
        float r = v - __bfloat162float(h);
        size_t o = jb.off + (size_t)(nt * 32 + row) * jb.K + kt * 32 + tx;
        wh[o] = h;
        wl[o] = __float2bfloat16(r);
    }
}

// ---------------- single-CTA CSR build (block syncs only) ----------------
// smem counters: q[0:128) d[128:1152) mq[1152:1280) md[1280:2304)
__global__ void __launch_bounds__(1024)
csr_build_kernel(const int* __restrict__ qsrc, const int* __restrict__ qdst, int EQ,
                 const int* __restrict__ dsrc, const int* __restrict__ ddst, int ED,
                 const int* __restrict__ qi, const int* __restrict__ di, int EM)
{
    __shared__ int sc[2304];
    const int t = threadIdx.x;
    // zero
    for (int i = t; i < 2304; i += 1024) sc[i] = 0;
    __syncthreads();
    // count
    for (int e = t; e < EQ; e += 1024) atomicAdd(&sc[qdst[e]], 1);
    for (int e = t; e < ED; e += 1024) atomicAdd(&sc[128 + ddst[e]], 1);
    for (int e = t; e < EM; e += 1024) atomicAdd(&sc[1152 + qi[e]], 1);
    for (int e = t; e < EM; e += 1024) atomicAdd(&sc[1280 + di[e]], 1);
    __syncthreads();
    // q segment scan (128)
    for (int o = 1; o < 128; o <<= 1) {
        int v = (t >= o && t < 128) ? sc[t - o] : 0;
        __syncthreads();
        if (t < 128) sc[t] += v;
        __syncthreads();
    }
    if (t < 128) g_qoff[t + 1] = sc[t];
    __syncthreads();
    // mq segment scan (128)
    for (int o = 1; o < 128; o <<= 1) {
        int v = (t >= o && t < 128) ? sc[1152 + t - o] : 0;
        __syncthreads();
        if (t < 128) sc[1152 + t] += v;
        __syncthreads();
    }
    if (t < 128) g_mqoff[t + 1] = sc[1152 + t];
    __syncthreads();
    // d segment scan (1024)
    for (int o = 1; o < 1024; o <<= 1) {
        int v = (t >= o) ? sc[128 + t - o] : 0;
        __syncthreads();
        sc[128 + t] += v;
        __syncthreads();
    }
    g_doff[t + 1] = sc[128 + t];
    __syncthreads();
    // md segment scan (1024)
    for (int o = 1; o < 1024; o <<= 1) {
        int v = (t >= o) ? sc[1280 + t - o] : 0;
        __syncthreads();
        sc[1280 + t] += v;
        __syncthreads();
    }
    g_mdoff[t + 1] = sc[1280 + t];
    if (t == 0) { g_qoff[0] = 0; g_doff[0] = 0; g_mqoff[0] = 0; g_mdoff[0] = 0; }
    __syncthreads();
    // reset counters (cursors)
    for (int i = t; i < 2304; i += 1024) sc[i] = 0;
    __syncthreads();
    // fill (+ per-entry GCN coefficient; degrees from now-complete offsets)
    for (int e = t; e < EQ; e += 1024) {
        int s = qsrc[e], d = qdst[e];
        int p = g_qoff[d] + atomicAdd(&sc[d], 1);
        g_qsrcs[p] = s;
        float degs = (float)(g_qoff[s + 1] - g_qoff[s]) + 1.0f;
        float degd = (float)(g_qoff[d + 1] - g_qoff[d]) + 1.0f;
        g_qcoef[p] = rsqrtf(degs) * rsqrtf(degd);
    }
    for (int e = t; e < ED; e += 1024) {
        int s = dsrc[e], d = ddst[e];
        int p = g_doff[d] + atomicAdd(&sc[128 + d], 1);
        g_dsrcs[p] = s;
        float degs = (float)(g_doff[s + 1] - g_doff[s]) + 1.0f;
        float degd = (float)(g_doff[d + 1] - g_doff[d]) + 1.0f;
        g_dcoef[p] = rsqrtf(degs) * rsqrtf(degd);
    }
    for (int e = t; e < EM; e += 1024) {
        int q = qi[e];
        g_mql[g_mqoff[q] + atomicAdd(&sc[1152 + q], 1)] = make_int2(e, di[e]);
    }
    for (int e = t; e < EM; e += 1024) {
        int d = di[e];
        g_mdl[g_mdoff[d] + atomicAdd(&sc[1280 + d], 1)] = make_int2(e, qi[e]);
    }
}

// ---------------- HMMA split-bf16 GEMM, 64x64 tiles (R6/R7, unchanged) ----------------
struct GemmJob {
    const float* A;
    const __nv_bfloat16* Bh;
    const __nv_bfloat16* Bl;
    float* C;
    const float* bias;
    int M, N, K, lda, ldc;
};

#define HG_A    0
#define HG_ASTR 288
#define HG_BH   18432
#define HG_BL   27648
#define HG_BSTR 144
#define HG_SMEM 36864

__global__ void __launch_bounds__(256, 2)
hgemm_kernel(GemmJob j0, GemmJob j1)
{
    GemmJob jb = (blockIdx.z == 0) ? j0 : j1;
    const int n0 = blockIdx.x * 64;
    const int m0 = blockIdx.y * 64;
    if (n0 >= jb.N || m0 >= jb.M) return;
    extern __shared__ char sm[];
    const int t = threadIdx.x, lane = t & 31, wid = t >> 5;
    const int warp_m = wid & 1, warp_n = wid >> 1;
    const int qr = lane >> 2, qk = (lane & 3) * 2;
    float acc[2][2][4] = {};

    for (int kc = 0; kc < jb.K; kc += 64) {
        __syncthreads();
        {
            int row = t >> 2, c4 = (t & 3) * 4;
            const float4* src = (const float4*)(jb.A + (size_t)(m0 + row) * jb.lda + kc) + c4;
            float4* dst = (float4*)(sm + HG_A + row * HG_ASTR + c4 * 16);
            #pragma unroll
            for (int i = 0; i < 4; i++) dst[i] = src[i];
        }
        #pragma unroll
        for (int p = 0; p < 2; p++) {
            int idx = t + p * 256;
            int row = idx >> 3, c = idx & 7;
            size_t go = (size_t)(n0 + row) * jb.K + kc + c * 8;
            *(uint4*)(sm + HG_BH + row * HG_BSTR + c * 16) = *(const uint4*)(jb.Bh + go);
            *(uint4*)(sm + HG_BL + row * HG_BSTR + c * 16) = *(const uint4*)(jb.Bl + go);
        }
        __syncthreads();
        #pragma unroll
        for (int kk = 0; kk < 64; kk += 16) {
            uint32_t bh[2][2], bl[2][2];
            #pragma unroll
            for (int f = 0; f < 2; f++) {
                int n = warp_n * 16 + f * 8 + qr;
                const char* bp = sm + n * HG_BSTR + (kk + qk) * 2;
                bh[f][0] = *(const uint32_t*)(bp + HG_BH);
                bh[f][1] = *(const uint32_t*)(bp + HG_BH + 16);
                bl[f][0] = *(const uint32_t*)(bp + HG_BL);
                bl[f][1] = *(const uint32_t*)(bp + HG_BL + 16);
            }
            #pragma unroll
            for (int s = 0; s < 2; s++) {
                int r = warp_m * 32 + s * 16 + qr;
                const char* ap = sm + HG_A + r * HG_ASTR + (kk + qk) * 4;
                float2 a0 = *(const float2*)ap;
                float2 a1 = *(const float2*)(ap + 8 * HG_ASTR);
                float2 a2 = *(const float2*)(ap + 32);
                float2 a3 = *(const float2*)(ap + 8 * HG_ASTR + 32);
                uint32_t ah[4], al[4];
                split_pack(a0.x, a0.y, ah[0], al[0]);
                split_pack(a1.x, a1.y, ah[1], al[1]);
                split_pack(a2.x, a2.y, ah[2], al[2]);
                split_pack(a3.x, a3.y, ah[3], al[3]);
                #pragma unroll
                for (int f = 0; f < 2; f++) {
                    mma_bf16(acc[s][f], ah[0], ah[1], ah[2], ah[3], bh[f][0], bh[f][1]);
                    mma_bf16(acc[s][f], al[0], al[1], al[2], al[3], bh[f][0], bh[f][1]);
                    mma_bf16(acc[s][f], ah[0], ah[1], ah[2], ah[3], bl[f][0], bl[f][1]);
                }
            }
        }
    }
    #pragma unroll
    for (int s = 0; s < 2; s++) {
        int r = m0 + warp_m * 32 + s * 16 + qr;
        #pragma unroll
        for (int f = 0; f < 2; f++) {
            int n = n0 + warp_n * 16 + f * 8 + qk;
            float bs0 = jb.bias ? jb.bias[n] : 0.0f;
            float bs1 = jb.bias ? jb.bias[n + 1] : 0.0f;
            float2 v0 = { acc[s][f][0] + bs0, acc[s][f][1] + bs1 };
            float2 v1 = { acc[s][f][2] + bs0, acc[s][f][3] + bs1 };
            *(float2*)(jb.C + (size_t)r * jb.ldc + n) = v0;
            *(float2*)(jb.C + (size_t)(r + 8) * jb.ldc + n) = v1;
        }
    }
}

// ---------------- GCN gather (R10, unchanged) ----------------
__global__ void gcn_gather_kernel(const float* __restrict__ qh, const float* __restrict__ dh,
                                  const float* __restrict__ qb, const float* __restrict__ db,
                                  float* __restrict__ qout, float* __restrict__ dout)
{
    const float4 z4 = {0.f, 0.f, 0.f, 0.f};
    int v = blockIdx.x * blockDim.x + threadIdx.x;
    const float* h; const float* b; float* out;
    const int* off; const int* srcs; const float* coefs; int node;
    if (v < NQ * 64) {
        node = v >> 6; h = qh; b = qb; out = qout;
        off = g_qoff; srcs = g_qsrcs; coefs = g_qcoef;
    } else if (v < (NQ + ND) * 64) {
        v -= NQ * 64;
        node = v >> 6; h = dh; b = db; out = dout;
        off = g_doff; srcs = g_dsrcs; coefs = g_dcoef;
    } else return;
    int c = v & 63;
    int lo = off[node], hi = off[node + 1];
    float invd = 1.0f / ((float)(hi - lo) + 1.0f);
    float4 hh = ((const float4*)h)[node * 64 + c];
    float4 bb = ((const float4*)b)[c];
    float4 acc0 = { hh.x * invd + bb.x, hh.y * invd + bb.y,
                    hh.z * invd + bb.z, hh.w * invd + bb.w };
    float4 acc1 = z4;
    int k = lo;
    for (; k + 2 <= hi; k += 2) {
        int s0 = srcs[k], s1 = srcs[k + 1];
        float c0 = coefs[k], c1 = coefs[k + 1];
        float4 h0 = ((const float4*)h)[s0 * 64 + c];
        float4 h1 = ((const float4*)h)[s1 * 64 + c];
        acc0.x += c0 * h0.x; acc0.y += c0 * h0.y;
        acc0.z += c0 * h0.z; acc0.w += c0 * h0.w;
        acc1.x += c1 * h1.x; acc1.y += c1 * h1.y;
        acc1.z += c1 * h1.z; acc1.w += c1 * h1.w;
    }
    if (k < hi) {
        int s0 = srcs[k];
        float c0 = coefs[k];
        float4 h0 = ((const float4*)h)[s0 * 64 + c];
        acc0.x += c0 * h0.x; acc0.y += c0 * h0.y;
        acc0.z += c0 * h0.z; acc0.w += c0 * h0.w;
    }
    acc0.x = fmaxf(acc0.x + acc1.x, 0.f);
    acc0.y = fmaxf(acc0.y + acc1.y, 0.f);
    acc0.z = fmaxf(acc0.z + acc1.z, 0.f);
    acc0.w = fmaxf(acc0.w + acc1.w, 0.f);
    ((float4*)out)[node * 128 + c] = acc0;
    ((float4*)out)[node * 128 + 64 + c] = z4;
}

// ---------------- cross-matching kernels (R10, unchanged) ----------------
__global__ void cos_norm_kernel(const int* __restrict__ qi, const int* __restrict__ di, int E,
                                const float* __restrict__ qbuf, const float* __restrict__ dbuf,
                                float* __restrict__ cosw)
{
    int e = blockIdx.x * (blockDim.x >> 5) + (threadIdx.x >> 5);
    int lane = threadIdx.x & 31;
    if (e >= E) return;
    const float* qp = qbuf + qi[e] * CAT;
    const float* dp = dbuf + di[e] * CAT;
    float qq = 0.f, dd = 0.f, qd = 0.f;
    for (int k = lane; k < DD; k += 32) {
        float a = qp[k], b = dp[k];
        qq += a * a; dd += b * b; qd += a * b;
    }
    #pragma unroll
    for (int o = 16; o; o >>= 1) {
        qq += __shfl_xor_sync(0xFFFFFFFFu, qq, o);
        dd += __shfl_xor_sync(0xFFFFFFFFu, dd, o);
        qd += __shfl_xor_sync(0xFFFFFFFFu, qd, o);
    }
    if (lane == 0)
        cosw[e] = qd / (fmaxf(sqrtf(qq), 1e-8f) * fmaxf(sqrtf(dd), 1e-8f));
}

__global__ void softmax_kernel(float* __restrict__ cosw, int E)
{
    __shared__ float red[1024];
    int t = threadIdx.x;
    float m = -1e30f;
    for (int e = t; e < E; e += 1024) m = fmaxf(m, cosw[e]);
    red[t] = m; __syncthreads();
    for (int s = 512; s; s >>= 1) { if (t < s) red[t] = fmaxf(red[t], red[t + s]); __syncthreads(); }
    float mx = red[0]; __syncthreads();
    float sum = 0.f;
    for (int e = t; e < E; e += 1024) sum += expf(cosw[e] - mx);
    red[t] = sum; __syncthreads();
    for (int s = 512; s; s >>= 1) { if (t < s) red[t] += red[t + s]; __syncthreads(); }
    float inv = 1.0f / red[0];
    for (int e = t; e < E; e += 1024) cosw[e] = expf(cosw[e] - mx) * inv;
}

__global__ void cross_gather_kernel(float* __restrict__ qbuf, float* __restrict__ dbuf,
                                    const float* __restrict__ w)
{
    const float4 z4 = {0.f, 0.f, 0.f, 0.f};
    int v = blockIdx.x * blockDim.x + threadIdx.x;
    const float* rd; float* wrbuf; const int* off; const int2* list; int node;
    if (v < NQ * 64) {
        node = v >> 6; rd = dbuf; wrbuf = qbuf; off = g_mqoff; list = g_mql;
    } else if (v < (NQ + ND) * 64) {
        v -= NQ * 64;
        node = v >> 6; rd = qbuf; wrbuf = dbuf; off = g_mdoff; list = g_mdl;
    } else return;
    int c = v & 63;
    int lo = off[node], hi = off[node + 1];
    float4 acc0 = z4, acc1 = z4;
    int k = lo;
    for (; k + 2 <= hi; k += 2) {
        int2 p0 = list[k], p1 = list[k + 1];
        float w0 = w[p0.x], w1 = w[p1.x];
        float4 v0 = ((const float4*)rd)[p0.y * 128 + c];
        float4 v1 = ((const float4*)rd)[p1.y * 128 + c];
        acc0.x += w0 * v0.x; acc0.y += w0 * v0.y;
        acc0.z += w0 * v0.z; acc0.w += w0 * v0.w;
        acc1.x += w1 * v1.x; acc1.y += w1 * v1.y;
        acc1.z += w1 * v1.z; acc1.w += w1 * v1.w;
    }
    if (k < hi) {
        int2 p0 = list[k];
        float w0 = w[p0.x];
        float4 v0 = ((const float4*)rd)[p0.y * 128 + c];
        acc0.x += w0 * v0.x; acc0.y += w0 * v0.y;
        acc0.z += w0 * v0.z; acc0.w += w0 * v0.w;
    }
    acc0.x += acc1.x; acc0.y += acc1.y; acc0.z += acc1.z; acc0.w += acc1.w;
    ((float4*)wrbuf)[node * 128 + 64 + c] = acc0;
}

// ---------------- HMMA pair-MLP: 3-pass split, preloaded Bq, 1 sync/iter (R12) ----
#define SM_BQ   0
#define SM_B3   8192
#define SM_W4   8704
#define SM_RED  9216
#define SM_BD   12288
#define BD_STR  1032
#define SM_W3H  (SM_BD + 64 * BD_STR)           // 78336
#define W3_STR  528
#define SM_W3L  (SM_W3H + 128 * W3_STR)         // 145920
#define SM_PAIR_TOTAL (SM_W3L + 128 * W3_STR)   // 213504

__global__ void __launch_bounds__(512, 1)
pair_hmma_kernel(const float* __restrict__ Bq, const float* __restrict__ Bd,
                 const __nv_bfloat16* __restrict__ w3hi, const __nv_bfloat16* __restrict__ w3lo,
                 const float* __restrict__ b3, const float* __restrict__ w4,
                 const float* __restrict__ b4, float* __restrict__ pred)
{
    extern __shared__ char smem[];
    const int t = threadIdx.x, lane = t & 31, wid = t >> 5;
    const int warp_m = wid & 3, warp_n = wid >> 2;
    const int j0 = blockIdx.x * 64;
    const int i0 = blockIdx.y * 8;

    ((uint4*)(smem + SM_BQ))[t] = ((const uint4*)(Bq + (size_t)i0 * DD))[t];
    for (int v = t; v < 64 * 128; v += 512) {
        int row = v >> 7, c = v & 127;
        *(float2*)(smem + SM_BD + row * BD_STR + c * 8) =
            ((const float2*)(Bd + (size_t)(j0 + row) * DD))[c];
    }
    for (int v = t; v < 128 * 32; v += 512) {
        int row = v >> 5, c = v & 31;
        *(uint4*)(smem + SM_W3H + row * W3_STR + c * 16) =
            ((const uint4*)(w3hi + (size_t)row * DD))[c];
        *(uint4*)(smem + SM_W3L + row * W3_STR + c * 16) =
            ((const uint4*)(w3lo + (size_t)row * DD))[c];
    }
    if (t < 32) ((uint4*)(smem + SM_B3))[t] = ((const uint4*)b3)[t];
    else if (t < 64) ((uint4*)(smem + SM_W4))[t - 32] = ((const uint4*)w4)[t - 32];
    const float b4v = b4[0];
    __syncthreads();

    const float* b3s = (const float*)(smem + SM_B3);
    const float* w4s = (const float*)(smem + SM_W4);

    const int r_lo = warp_m * 16 + (lane >> 2);
    const char* bd_lo = smem + SM_BD + r_lo * BD_STR;
    const char* bd_hi = bd_lo + 8 * BD_STR;
    const int kq = (lane & 3) * 2;
    const int nrow = warp_n * 32 + (lane >> 2);

    for (int il = 0; il < 8; il++) {
        const char* bqrow = smem + SM_BQ + il * 1024;
        float c[4][4];
        #pragma unroll
        for (int nt = 0; nt < 4; nt++)
            #pragma unroll
            for (int u = 0; u < 4; u++) c[nt][u] = 0.0f;

        #pragma unroll
        for (int ks = 0; ks < 16; ks++) {
            const int kb = ks * 16 + kq;
            float2 q0 = *(const float2*)(bqrow + kb * 4);
            float2 q1 = *(const float2*)(bqrow + (kb + 8) * 4);
            uint32_t ah[4], al[4];
            {
                float2 d = *(const float2*)(bd_lo + kb * 4);
                split_pack(fmaxf(d.x + q0.x, 0.0f), fmaxf(d.y + q0.y, 0.0f), ah[0], al[0]);
            }
            {
                float2 d = *(const float2*)(bd_hi + kb * 4);
                split_pack(fmaxf(d.x + q0.x, 0.0f), fmaxf(d.y + q0.y, 0.0f), ah[1], al[1]);
            }
            {
                float2 d = *(const float2*)(bd_lo + (kb + 8) * 4);
                split_pack(fmaxf(d.x + q1.x, 0.0f), fmaxf(d.y + q1.y, 0.0f), ah[2], al[2]);
            }
            {
                float2 d = *(const float2*)(bd_hi + (kb + 8) * 4);
                split_pack(fmaxf(d.x + q1.x, 0.0f), fmaxf(d.y + q1.y, 0.0f), ah[3], al[3]);
            }
            #pragma unroll
            for (int nt = 0; nt < 4; nt++) {
                const int roff = (nrow + nt * 8) * W3_STR + kb * 2;
                uint32_t bh0 = *(const uint32_t*)(smem + SM_W3H + roff);
                uint32_t bh1 = *(const uint32_t*)(smem + SM_W3H + roff + 16);
                uint32_t bl0 = *(const uint32_t*)(smem + SM_W3L + roff);
                uint32_t bl1 = *(const uint32_t*)(smem + SM_W3L + roff + 16);
                mma_bf16(c[nt], ah[0], ah[1], ah[2], ah[3], bh0, bh1);
                mma_bf16(c[nt], al[0], al[1], al[2], al[3], bh0, bh1);
                mma_bf16(c[nt], ah[0], ah[1], ah[2], ah[3], bl0, bl1);
            }
        }

        float* redb = (float*)(smem + SM_RED) + (il & 1) * 256;
        float s_lo = 0.0f, s_hi = 0.0f;
        #pragma unroll
        for (int nt = 0; nt < 4; nt++) {
            int n0 = warp_n * 32 + nt * 8 + (lane & 3) * 2;
            float b30 = b3s[n0], b31 = b3s[n0 + 1];
            float w40 = w4s[n0], w41 = w4s[n0 + 1];
            s_lo += fmaxf(c[nt][0] + b30, 0.0f) * w40 + fmaxf(c[nt][1] + b31, 0.0f) * w41;
            s_hi += fmaxf(c[nt][2] + b30, 0.0f) * w40 + fmaxf(c[nt][3] + b31, 0.0f) * w41;
        }
        s_lo += __shfl_xor_sync(0xFFFFFFFFu, s_lo, 1);
        s_lo += __shfl_xor_sync(0xFFFFFFFFu, s_lo, 2);
        s_hi += __shfl_xor_sync(0xFFFFFFFFu, s_hi, 1);
        s_hi += __shfl_xor_sync(0xFFFFFFFFu, s_hi, 2);
        if ((lane & 3) == 0) {
            redb[r_lo * 4 + warp_n] = s_lo;
            redb[(r_lo + 8) * 4 + warp_n] = s_hi;
        }
        __syncthreads();
        if (t < 64) {
            float v = redb[t * 4] + redb[t * 4 + 1] + redb[t * 4 + 2] + redb[t * 4 + 3] + b4v;
            v = v > 0.0f ? v : 0.0f;
            pred[(size_t)(i0 + il) * ND + j0 + t] = v;
        }
    }
}

// ---------------- host orchestration ----------------
extern "C" void kernel_launch(void* const* d_in, const int* in_sizes, int n_in,
                              void* d_out, int out_size)
{
    const float* qfeat = (const float*)d_in[0];
    const float* dfeat = (const float*)d_in[1];
    const int*   qe    = (const int*)d_in[2];
    const int*   de    = (const int*)d_in[3];
    const int*   qi    = (const int*)d_in[4];
    const int*   di    = (const int*)d_in[5];
    const float* q_w0 = (const float*)d_in[6];
    const float* q_b0 = (const float*)d_in[7];
    const float* q_w1 = (const float*)d_in[8];
    const float* q_b1 = (const float*)d_in[9];
    const float* d_w0 = (const float*)d_in[10];
    const float* d_b0 = (const float*)d_in[11];
    const float* d_w1 = (const float*)d_in[12];
    const float* d_b1 = (const float*)d_in[13];
    const float* w1 = (const float*)d_in[14];
    const float* b1 = (const float*)d_in[15];
    const float* w2 = (const float*)d_in[16];
    const float* b2 = (const float*)d_in[17];
    const float* w3 = (const float*)d_in[18];
    const float* b3 = (const float*)d_in[19];
    const float* w4 = (const float*)d_in[20];
    const float* b4 = (const float*)d_in[21];

    const int EQ = in_sizes[2] / 2;
    const int ED = in_sizes[3] / 2;
    const int EM = in_sizes[4];

    float *qh, *dh, *qB, *dB, *cosw, *Bqp, *Bdp;
    __nv_bfloat16 *wh, *wl;
    cudaGetSymbolAddress((void**)&qh, g_qh);
    cudaGetSymbolAddress((void**)&dh, g_dh);
    cudaGetSymbolAddress((void**)&qB, g_qB);
    cudaGetSymbolAddress((void**)&dB, g_dB);
    cudaGetSymbolAddress((void**)&cosw, g_cosw);
    cudaGetSymbolAddress((void**)&Bqp, g_Bq);
    cudaGetSymbolAddress((void**)&Bdp, g_Bd);
    cudaGetSymbolAddress((void**)&wh, g_wh);
    cudaGetSymbolAddress((void**)&wl, g_wl);

    float* out = (float*)d_out;
    float* qOut = out + NQ * ND;
    float* dOut = qOut + NQ * CAT;

    cudaFuncSetAttribute(hgemm_kernel, cudaFuncAttributeMaxDynamicSharedMemorySize, HG_SMEM);
    cudaFuncSetAttribute(pair_hmma_kernel, cudaFuncAttributeMaxDynamicSharedMemorySize,
                         SM_PAIR_TOTAL);

    // ---- 1. pack all weights ----
    PackArgs pa;
    pa.j[0] = { q_w0,               DD,  DD,  DD,  OFF_QW0 };
    pa.j[1] = { d_w0,               DD,  DD,  DD,  OFF_DW0 };
    pa.j[2] = { q_w1,               CAT, DD,  DD,  OFF_QW1 };
    pa.j[3] = { d_w1,               CAT, DD,  DD,  OFF_DW1 };
    pa.j[4] = { w1,                 CAT, CAT, CAT, OFF_W1T };
    pa.j[5] = { w1 + CAT * CAT,     CAT, CAT, CAT, OFF_W1B };
    pa.j[6] = { w2,                 CAT, DD,  DD,  OFF_W2  };
    pa.j[7] = { w3,                 DD,  128, 128, OFF_W3  };
    pack_kernel<<<dim3(256, 8), 256>>>(pa, wh, wl);

    // ---- 2. CSR build (single CTA, block syncs only) ----
    csr_build_kernel<<<1, 1024>>>(qe, qe + EQ, EQ, de, de + ED, ED, qi, di, EM);

    const int nodeBlocks = (NQ + ND) * 64 / 256;

    // ---- 3. layer 0 ----
    {
        GemmJob jq = { qfeat, wh + OFF_QW0, wl + OFF_QW0, qh, nullptr, NQ, DD, DD, DD, DD };
        GemmJob jd = { dfeat, wh + OFF_DW0, wl + OFF_DW0, dh, nullptr, ND, DD, DD, DD, DD };
        hgemm_kernel<<<dim3(DD / 64, ND / 64, 2), 256, HG_SMEM>>>(jq, jd);
    }
    gcn_gather_kernel<<<nodeBlocks, 256>>>(qh, dh, q_b0, d_b0, qB, dB);
    cos_norm_kernel<<<(EM + 7) / 8, 256>>>(qi, di, EM, qB, dB, cosw);
    softmax_kernel<<<1, 1024>>>(cosw, EM);
    cross_gather_kernel<<<nodeBlocks, 256>>>(qB, dB, cosw);

    // ---- 4. layer 1 (outputs straight into d_out) ----
    {
        GemmJob jq = { qB, wh + OFF_QW1, wl + OFF_QW1, qh, nullptr, NQ, DD, CAT, CAT, DD };
        GemmJob jd = { dB, wh + OFF_DW1, wl + OFF_DW1, dh, nullptr, ND, DD, CAT, CAT, DD };
        hgemm_kernel<<<dim3(DD / 64, ND / 64, 2), 256, HG_SMEM>>>(jq, jd);
    }
    gcn_gather_kernel<<<nodeBlocks, 256>>>(qh, dh, q_b1, d_b1, qOut, dOut);
    cos_norm_kernel<<<(EM + 7) / 8, 256>>>(qi, di, EM, qOut, dOut, cosw);
    softmax_kernel<<<1, 1024>>>(cosw, EM);
    cross_gather_kernel<<<nodeBlocks, 256>>>(qOut, dOut, cosw);

    // ---- 5. final scoring (w1/w2 folded) ----
    {
        GemmJob jq = { qOut, wh + OFF_W1T, wl + OFF_W1T, qB, b1, NQ, CAT, CAT, CAT, CAT };
        GemmJob jd = { dOut, wh + OFF_W1B, wl + OFF_W1B, dB, nullptr, ND, CAT, CAT, CAT, CAT };
        hgemm_kernel<<<dim3(CAT / 64, ND / 64, 2), 256, HG_SMEM>>>(jq, jd);
    }
    {
        GemmJob jq = { qB, wh + OFF_W2, wl + OFF_W2, Bqp, b2, NQ, DD, CAT, CAT, DD };
        GemmJob jd = { dB, wh + OFF_W2, wl + OFF_W2, Bdp, nullptr, ND, DD, CAT, CAT, DD };
        hgemm_kernel<<<dim3(DD / 64, ND / 64, 2), 256, HG_SMEM>>>(jq, jd);
    }

    // ---- 6. pair MLP -> pred ----
    dim3 pg(ND / 64, NQ / 8);
    pair_hmma_kernel<<<pg, 512, SM_PAIR_TOTAL>>>(Bqp, Bdp, wh + OFF_W3, wl + OFF_W3,
                                                 b3, w4, b4, out);
}

// round 15
// speedup vs baseline: 1.2388x; 1.2388x over previous
#include <cuda_runtime.h>
#include <cuda_bf16.h>
#include <cstdint>
#include <math.h>

#define NQ 128
#define ND 1024
#define DD 256
#define CAT 512
#define EQMAX 2048
#define EDMAX 32768
#define EMMAX 8192

// ---------------- device scratch ----------------
__device__ float g_qh[NQ * DD];
__device__ float g_dh[ND * DD];
__device__ float g_qB[NQ * CAT];
__device__ float g_dB[ND * CAT];
__device__ float g_cosw[EMMAX];
__device__ float g_Bq[NQ * DD];
__device__ float g_Bd[ND * DD];

// CSR structures (static graphs -> built once per run)
__device__ int   g_qcnt[NQ],  g_qoff[NQ + 1],  g_qsrcs[EQMAX];
__device__ float g_qcoef[EQMAX];
__device__ int   g_dcnt[ND],  g_doff[ND + 1],  g_dsrcs[EDMAX];
__device__ float g_dcoef[EDMAX];
__device__ int   g_mqcnt[NQ], g_mqoff[NQ + 1];
__device__ int2  g_mql[EMMAX];            // (edge, d-node)
__device__ int   g_mdcnt[ND], g_mdoff[ND + 1];
__device__ int2  g_mdl[EMMAX];            // (edge, q-node)

// packed weights: [N][K] bf16, hi and lo parts
#define OFF_QW0 0
#define OFF_DW0 65536
#define OFF_QW1 131072
#define OFF_DW1 262144
#define OFF_W1T 393216
#define OFF_W1B 655360
#define OFF_W2  917504
#define OFF_W3  1048576
#define WPACK_TOTAL 1081344
__device__ __align__(16) __nv_bfloat16 g_wh[WPACK_TOTAL];
__device__ __align__(16) __nv_bfloat16 g_wl[WPACK_TOTAL];

// ---------------- shared helpers ----------------
__device__ __forceinline__ void mma_bf16(float c[4],
                                         uint32_t a0, uint32_t a1, uint32_t a2, uint32_t a3,
                                         uint32_t b0, uint32_t b1)
{
    asm volatile("mma.sync.aligned.m16n8k16.row.col.f32.bf16.bf16.f32 "
                 "{%0,%1,%2,%3}, {%4,%5,%6,%7}, {%8,%9}, {%0,%1,%2,%3};"
                 : "+f"(c[0]), "+f"(c[1]), "+f"(c[2]), "+f"(c[3])
                 : "r"(a0), "r"(a1), "r"(a2), "r"(a3), "r"(b0), "r"(b1));
}

__device__ __forceinline__ void split_pack(float v0, float v1, uint32_t& hi, uint32_t& lo)
{
    asm("cvt.rn.bf16x2.f32 %0, %1, %2;" : "=r"(hi) : "f"(v1), "f"(v0));
    float h0 = __uint_as_float(hi << 16);
    float h1 = __uint_as_float(hi & 0xffff0000u);
    float r0 = v0 - h0, r1 = v1 - h1;
    asm("cvt.rn.bf16x2.f32 %0, %1, %2;" : "=r"(lo) : "f"(r1), "f"(r0));
}

// ---------------- weight pack: transpose + bf16 split ----------------
struct PackJob { const float* src; int K, N, ld; int64_t off; };
struct PackArgs { PackJob j[8]; };

__global__ void pack_kernel(PackArgs pa, __nv_bfloat16* __restrict__ wh,
                            __nv_bfloat16* __restrict__ wl)
{
    __shared__ float tile[32][33];
    const PackJob jb = pa.j[blockIdx.y];
    int ntilesK = jb.K >> 5;
    int ntiles = ntilesK * (jb.N >> 5);
    if ((int)blockIdx.x >= ntiles) return;
    int kt = blockIdx.x % ntilesK, nt = blockIdx.x / ntilesK;
    int tx = threadIdx.x & 31, ty = threadIdx.x >> 5;
    #pragma unroll
    for (int p = 0; p < 4; p++) {
        int row = ty + p * 8;
        tile[row][tx] = jb.src[(size_t)(kt * 32 + row) * jb.ld + nt * 32 + tx];
    }
    __syncthreads();
    #pragma unroll
    for (int p = 0; p < 4; p++) {
        int row = ty + p * 8;
        float v = tile[tx][row];
        __nv_bfloat16 h = __float2bfloat16(v);
        float r = v - __bfloat162float(h);
        size_t o = jb.off + (size_t)(nt * 32 + row) * jb.K + kt * 32 + tx;
        wh[o] = h;
        wl[o] = __float2bfloat16(r);
    }
}

// ---------------- CSR build (R12 4-kernel chain, unchanged) ----------------
__global__ void csr_zero_kernel()
{
    int i = blockIdx.x * blockDim.x + threadIdx.x;
    if (i < NQ) { g_qcnt[i] = 0; g_mqcnt[i] = 0; }
    if (i < ND) { g_dcnt[i] = 0; g_mdcnt[i] = 0; }
}

__global__ void csr_count_kernel(const int* __restrict__ qdst, int EQ,
                                 const int* __restrict__ ddst, int ED,
                                 const int* __restrict__ qi, const int* __restrict__ di, int EM)
{
    int e = blockIdx.x * blockDim.x + threadIdx.x;
    if (e < EQ) atomicAdd(&g_qcnt[qdst[e]], 1);
    else if (e < EQ + ED) atomicAdd(&g_dcnt[ddst[e - EQ]], 1);
    else if (e < EQ + ED + EM) atomicAdd(&g_mqcnt[qi[e - EQ - ED]], 1);
    else if (e < EQ + ED + 2 * EM) atomicAdd(&g_mdcnt[di[e - EQ - ED - EM]], 1);
}

__global__ void __launch_bounds__(1024) csr_scan_kernel()
{
    __shared__ int s[1024];
    int* cnt; int* off; int n;
    switch (blockIdx.x) {
        case 0: cnt = g_qcnt;  off = g_qoff;  n = NQ; break;
        case 1: cnt = g_dcnt;  off = g_doff;  n = ND; break;
        case 2: cnt = g_mqcnt; off = g_mqoff; n = NQ; break;
        default: cnt = g_mdcnt; off = g_mdoff; n = ND; break;
    }
    int t = threadIdx.x;
    s[t] = (t < n) ? cnt[t] : 0;
    __syncthreads();
    for (int o = 1; o < 1024; o <<= 1) {
        int v = (t >= o) ? s[t - o] : 0;
        __syncthreads();
        s[t] += v;
        __syncthreads();
    }
    if (t < n) {
        off[t + 1] = s[t];
        if (t == 0) off[0] = 0;
        cnt[t] = 0;
    }
}

__global__ void csr_fill_kernel(const int* __restrict__ qsrc, const int* __restrict__ qdst, int EQ,
                                const int* __restrict__ dsrc, const int* __restrict__ ddst, int ED,
                                const int* __restrict__ qi, const int* __restrict__ di, int EM)
{
    int e = blockIdx.x * blockDim.x + threadIdx.x;
    if (e < EQ) {
        int s = qsrc[e], d = qdst[e];
        int p = g_qoff[d] + atomicAdd(&g_qcnt[d], 1);
        g_qsrcs[p] = s;
        float degs = (float)(g_qoff[s + 1] - g_qoff[s]) + 1.0f;
        float degd = (float)(g_qoff[d + 1] - g_qoff[d]) + 1.0f;
        g_qcoef[p] = rsqrtf(degs) * rsqrtf(degd);
    } else if (e < EQ + ED) {
        int w = e - EQ;
        int s = dsrc[w], d = ddst[w];
        int p = g_doff[d] + atomicAdd(&g_dcnt[d], 1);
        g_dsrcs[p] = s;
        float degs = (float)(g_doff[s + 1] - g_doff[s]) + 1.0f;
        float degd = (float)(g_doff[d + 1] - g_doff[d]) + 1.0f;
        g_dcoef[p] = rsqrtf(degs) * rsqrtf(degd);
    } else if (e < EQ + ED + EM) {
        int w = e - EQ - ED;
        int q = qi[w];
        int p = g_mqoff[q] + atomicAdd(&g_mqcnt[q], 1);
        g_mql[p] = make_int2(w, di[w]);
    } else if (e < EQ + ED + 2 * EM) {
        int w = e - EQ - ED - EM;
        int d = di[w];
        int p = g_mdoff[d] + atomicAdd(&g_mdcnt[d], 1);
        g_mdl[p] = make_int2(w, qi[w]);
    }
}

// ---------------- HMMA split-bf16 GEMM, 64x64 tiles (R6/R7, unchanged) ----------------
struct GemmJob {
    const float* A;
    const __nv_bfloat16* Bh;
    const __nv_bfloat16* Bl;
    float* C;
    const float* bias;
    int M, N, K, lda, ldc;
};

#define HG_A    0
#define HG_ASTR 288
#define HG_BH   18432
#define HG_BL   27648
#define HG_BSTR 144
#define HG_SMEM 36864

__global__ void __launch_bounds__(256, 2)
hgemm_kernel(GemmJob j0, GemmJob j1)
{
    GemmJob jb = (blockIdx.z == 0) ? j0 : j1;
    const int n0 = blockIdx.x * 64;
    const int m0 = blockIdx.y * 64;
    if (n0 >= jb.N || m0 >= jb.M) return;
    extern __shared__ char sm[];
    const int t = threadIdx.x, lane = t & 31, wid = t >> 5;
    const int warp_m = wid & 1, warp_n = wid >> 1;
    const int qr = lane >> 2, qk = (lane & 3) * 2;
    float acc[2][2][4] = {};

    for (int kc = 0; kc < jb.K; kc += 64) {
        __syncthreads();
        {
            int row = t >> 2, c4 = (t & 3) * 4;
            const float4* src = (const float4*)(jb.A + (size_t)(m0 + row) * jb.lda + kc) + c4;
            float4* dst = (float4*)(sm + HG_A + row * HG_ASTR + c4 * 16);
            #pragma unroll
            for (int i = 0; i < 4; i++) dst[i] = src[i];
        }
        #pragma unroll
        for (int p = 0; p < 2; p++) {
            int idx = t + p * 256;
            int row = idx >> 3, c = idx & 7;
            size_t go = (size_t)(n0 + row) * jb.K + kc + c * 8;
            *(uint4*)(sm + HG_BH + row * HG_BSTR + c * 16) = *(const uint4*)(jb.Bh + go);
            *(uint4*)(sm + HG_BL + row * HG_BSTR + c * 16) = *(const uint4*)(jb.Bl + go);
        }
        __syncthreads();
        #pragma unroll
        for (int kk = 0; kk < 64; kk += 16) {
            uint32_t bh[2][2], bl[2][2];
            #pragma unroll
            for (int f = 0; f < 2; f++) {
                int n = warp_n * 16 + f * 8 + qr;
                const char* bp = sm + n * HG_BSTR + (kk + qk) * 2;
                bh[f][0] = *(const uint32_t*)(bp + HG_BH);
                bh[f][1] = *(const uint32_t*)(bp + HG_BH + 16);
                bl[f][0] = *(const uint32_t*)(bp + HG_BL);
                bl[f][1] = *(const uint32_t*)(bp + HG_BL + 16);
            }
            #pragma unroll
            for (int s = 0; s < 2; s++) {
                int r = warp_m * 32 + s * 16 + qr;
                const char* ap = sm + HG_A + r * HG_ASTR + (kk + qk) * 4;
                float2 a0 = *(const float2*)ap;
                float2 a1 = *(const float2*)(ap + 8 * HG_ASTR);
                float2 a2 = *(const float2*)(ap + 32);
                float2 a3 = *(const float2*)(ap + 8 * HG_ASTR + 32);
                uint32_t ah[4], al[4];
                split_pack(a0.x, a0.y, ah[0], al[0]);
                split_pack(a1.x, a1.y, ah[1], al[1]);
                split_pack(a2.x, a2.y, ah[2], al[2]);
                split_pack(a3.x, a3.y, ah[3], al[3]);
                #pragma unroll
                for (int f = 0; f < 2; f++) {
                    mma_bf16(acc[s][f], ah[0], ah[1], ah[2], ah[3], bh[f][0], bh[f][1]);
                    mma_bf16(acc[s][f], al[0], al[1], al[2], al[3], bh[f][0], bh[f][1]);
                    mma_bf16(acc[s][f], ah[0], ah[1], ah[2], ah[3], bl[f][0], bl[f][1]);
                }
            }
        }
    }
    #pragma unroll
    for (int s = 0; s < 2; s++) {
        int r = m0 + warp_m * 32 + s * 16 + qr;
        #pragma unroll
        for (int f = 0; f < 2; f++) {
            int n = n0 + warp_n * 16 + f * 8 + qk;
            float bs0 = jb.bias ? jb.bias[n] : 0.0f;
            float bs1 = jb.bias ? jb.bias[n + 1] : 0.0f;
            float2 v0 = { acc[s][f][0] + bs0, acc[s][f][1] + bs1 };
            float2 v1 = { acc[s][f][2] + bs0, acc[s][f][3] + bs1 };
            *(float2*)(jb.C + (size_t)r * jb.ldc + n) = v0;
            *(float2*)(jb.C + (size_t)(r + 8) * jb.ldc + n) = v1;
        }
    }
}

// ---------------- GCN gather: precomputed coefs + 4-way unroll ----------------
__global__ void gcn_gather_kernel(const float* __restrict__ qh, const float* __restrict__ dh,
                                  const float* __restrict__ qb, const float* __restrict__ db,
                                  float* __restrict__ qout, float* __restrict__ dout)
{
    const float4 z4 = {0.f, 0.f, 0.f, 0.f};
    int v = blockIdx.x * blockDim.x + threadIdx.x;
    const float* h; const float* b; float* out;
    const int* off; const int* srcs; const float* coefs; int node;
    if (v < NQ * 64) {
        node = v >> 6; h = qh; b = qb; out = qout;
        off = g_qoff; srcs = g_qsrcs; coefs = g_qcoef;
    } else if (v < (NQ + ND) * 64) {
        v -= NQ * 64;
        node = v >> 6; h = dh; b = db; out = dout;
        off = g_doff; srcs = g_dsrcs; coefs = g_dcoef;
    } else return;
    int c = v & 63;
    int lo = off[node], hi = off[node + 1];
    float invd = 1.0f / ((float)(hi - lo) + 1.0f);
    float4 hh = ((const float4*)h)[node * 64 + c];
    float4 bb = ((const float4*)b)[c];
    float4 acc0 = { hh.x * invd + bb.x, hh.y * invd + bb.y,
                    hh.z * invd + bb.z, hh.w * invd + bb.w };
    float4 acc1 = z4, acc2 = z4, acc3 = z4;
    int k = lo;
    for (; k + 4 <= hi; k += 4) {
        int s0 = srcs[k], s1 = srcs[k + 1], s2 = srcs[k + 2], s3 = srcs[k + 3];
        float c0 = coefs[k], c1 = coefs[k + 1], c2 = coefs[k + 2], c3 = coefs[k + 3];
        float4 h0 = ((const float4*)h)[s0 * 64 + c];
        float4 h1 = ((const float4*)h)[s1 * 64 + c];
        float4 h2 = ((const float4*)h)[s2 * 64 + c];
        float4 h3 = ((const float4*)h)[s3 * 64 + c];
        acc0.x += c0 * h0.x; acc0.y += c0 * h0.y; acc0.z += c0 * h0.z; acc0.w += c0 * h0.w;
        acc1.x += c1 * h1.x; acc1.y += c1 * h1.y; acc1.z += c1 * h1.z; acc1.w += c1 * h1.w;
        acc2.x += c2 * h2.x; acc2.y += c2 * h2.y; acc2.z += c2 * h2.z; acc2.w += c2 * h2.w;
        acc3.x += c3 * h3.x; acc3.y += c3 * h3.y; acc3.z += c3 * h3.z; acc3.w += c3 * h3.w;
    }
    for (; k < hi; k++) {
        int s0 = srcs[k];
        float c0 = coefs[k];
        float4 h0 = ((const float4*)h)[s0 * 64 + c];
        acc0.x += c0 * h0.x; acc0.y += c0 * h0.y; acc0.z += c0 * h0.z; acc0.w += c0 * h0.w;
    }
    acc0.x = fmaxf(acc0.x + acc1.x + acc2.x + acc3.x, 0.f);
    acc0.y = fmaxf(acc0.y + acc1.y + acc2.y + acc3.y, 0.f);
    acc0.z = fmaxf(acc0.z + acc1.z + acc2.z + acc3.z, 0.f);
    acc0.w = fmaxf(acc0.w + acc1.w + acc2.w + acc3.w, 0.f);
    ((float4*)out)[node * 128 + c] = acc0;
    ((float4*)out)[node * 128 + 64 + c] = z4;
}

// ---------------- cross-matching kernels (R12, unchanged) ----------------
__global__ void cos_norm_kernel(const int* __restrict__ qi, const int* __restrict__ di, int E,
                                const float* __restrict__ qbuf, const float* __restrict__ dbuf,
                                float* __restrict__ cosw)
{
    int e = blockIdx.x * (blockDim.x >> 5) + (threadIdx.x >> 5);
    int lane = threadIdx.x & 31;
    if (e >= E) return;
    const float* qp = qbuf + qi[e] * CAT;
    const float* dp = dbuf + di[e] * CAT;
    float qq = 0.f, dd = 0.f, qd = 0.f;
    for (int k = lane; k < DD; k += 32) {
        float a = qp[k], b = dp[k];
        qq += a * a; dd += b * b; qd += a * b;
    }
    #pragma unroll
    for (int o = 16; o; o >>= 1) {
        qq += __shfl_xor_sync(0xFFFFFFFFu, qq, o);
        dd += __shfl_xor_sync(0xFFFFFFFFu, dd, o);
        qd += __shfl_xor_sync(0xFFFFFFFFu, qd, o);
    }
    if (lane == 0)
        cosw[e] = qd / (fmaxf(sqrtf(qq), 1e-8f) * fmaxf(sqrtf(dd), 1e-8f));
}

__global__ void softmax_kernel(float* __restrict__ cosw, int E)
{
    __shared__ float red[1024];
    int t = threadIdx.x;
    float m = -1e30f;
    for (int e = t; e < E; e += 1024) m = fmaxf(m, cosw[e]);
    red[t] = m; __syncthreads();
    for (int s = 512; s; s >>= 1) { if (t < s) red[t] = fmaxf(red[t], red[t + s]); __syncthreads(); }
    float mx = red[0]; __syncthreads();
    float sum = 0.f;
    for (int e = t; e < E; e += 1024) sum += expf(cosw[e] - mx);
    red[t] = sum; __syncthreads();
    for (int s = 512; s; s >>= 1) { if (t < s) red[t] += red[t + s]; __syncthreads(); }
    float inv = 1.0f / red[0];
    for (int e = t; e < E; e += 1024) cosw[e] = expf(cosw[e] - mx) * inv;
}

__global__ void cross_gather_kernel(float* __restrict__ qbuf, float* __restrict__ dbuf,
                                    const float* __restrict__ w)
{
    const float4 z4 = {0.f, 0.f, 0.f, 0.f};
    int v = blockIdx.x * blockDim.x + threadIdx.x;
    const float* rd; float* wrbuf; const int* off; const int2* list; int node;
    if (v < NQ * 64) {
        node = v >> 6; rd = dbuf; wrbuf = qbuf; off = g_mqoff; list = g_mql;
    } else if (v < (NQ + ND) * 64) {
        v -= NQ * 64;
        node = v >> 6; rd = qbuf; wrbuf = dbuf; off = g_mdoff; list = g_mdl;
    } else return;
    int c = v & 63;
    int lo = off[node], hi = off[node + 1];
    float4 acc0 = z4, acc1 = z4;
    int k = lo;
    for (; k + 2 <= hi; k += 2) {
        int2 p0 = list[k], p1 = list[k + 1];
        float w0 = w[p0.x], w1 = w[p1.x];
        float4 v0 = ((const float4*)rd)[p0.y * 128 + c];
        float4 v1 = ((const float4*)rd)[p1.y * 128 + c];
        acc0.x += w0 * v0.x; acc0.y += w0 * v0.y;
        acc0.z += w0 * v0.z; acc0.w += w0 * v0.w;
        acc1.x += w1 * v1.x; acc1.y += w1 * v1.y;
        acc1.z += w1 * v1.z; acc1.w += w1 * v1.w;
    }
    if (k < hi) {
        int2 p0 = list[k];
        float w0 = w[p0.x];
        float4 v0 = ((const float4*)rd)[p0.y * 128 + c];
        acc0.x += w0 * v0.x; acc0.y += w0 * v0.y;
        acc0.z += w0 * v0.z; acc0.w += w0 * v0.w;
    }
    acc0.x += acc1.x; acc0.y += acc1.y; acc0.z += acc1.z; acc0.w += acc1.w;
    ((float4*)wrbuf)[node * 128 + 64 + c] = acc0;
}

// ---------------- HMMA pair-MLP: 3-pass split, preloaded Bq, 1 sync/iter (R12) ----
#define SM_BQ   0
#define SM_B3   8192
#define SM_W4   8704
#define SM_RED  9216
#define SM_BD   12288
#define BD_STR  1032
#define SM_W3H  (SM_BD + 64 * BD_STR)           // 78336
#define W3_STR  528
#define SM_W3L  (SM_W3H + 128 * W3_STR)         // 145920
#define SM_PAIR_TOTAL (SM_W3L + 128 * W3_STR)   // 213504

__global__ void __launch_bounds__(512, 1)
pair_hmma_kernel(const float* __restrict__ Bq, const float* __restrict__ Bd,
                 const __nv_bfloat16* __restrict__ w3hi, const __nv_bfloat16* __restrict__ w3lo,
                 const float* __restrict__ b3, const float* __restrict__ w4,
                 const float* __restrict__ b4, float* __restrict__ pred)
{
    extern __shared__ char smem[];
    const int t = threadIdx.x, lane = t & 31, wid = t >> 5;
    const int warp_m = wid & 3, warp_n = wid >> 2;
    const int j0 = blockIdx.x * 64;
    const int i0 = blockIdx.y * 8;

    ((uint4*)(smem + SM_BQ))[t] = ((const uint4*)(Bq + (size_t)i0 * DD))[t];
    for (int v = t; v < 64 * 128; v += 512) {
        int row = v >> 7, c = v & 127;
        *(float2*)(smem + SM_BD + row * BD_STR + c * 8) =
            ((const float2*)(Bd + (size_t)(j0 + row) * DD))[c];
    }
    for (int v = t; v < 128 * 32; v += 512) {
        int row = v >> 5, c = v & 31;
        *(uint4*)(smem + SM_W3H + row * W3_STR + c * 16) =
            ((const uint4*)(w3hi + (size_t)row * DD))[c];
        *(uint4*)(smem + SM_W3L + row * W3_STR + c * 16) =
            ((const uint4*)(w3lo + (size_t)row * DD))[c];
    }
    if (t < 32) ((uint4*)(smem + SM_B3))[t] = ((const uint4*)b3)[t];
    else if (t < 64) ((uint4*)(smem + SM_W4))[t - 32] = ((const uint4*)w4)[t - 32];
    const float b4v = b4[0];
    __syncthreads();

    const float* b3s = (const float*)(smem + SM_B3);
    const float* w4s = (const float*)(smem + SM_W4);

    const int r_lo = warp_m * 16 + (lane >> 2);
    const char* bd_lo = smem + SM_BD + r_lo * BD_STR;
    const char* bd_hi = bd_lo + 8 * BD_STR;
    const int kq = (lane & 3) * 2;
    const int nrow = warp_n * 32 + (lane >> 2);

    for (int il = 0; il < 8; il++) {
        const char* bqrow = smem + SM_BQ + il * 1024;
        float c[4][4];
        #pragma unroll
        for (int nt = 0; nt < 4; nt++)
            #pragma unroll
            for (int u = 0; u < 4; u++) c[nt][u] = 0.0f;

        #pragma unroll
        for (int ks = 0; ks < 16; ks++) {
            const int kb = ks * 16 + kq;
            float2 q0 = *(const float2*)(bqrow + kb * 4);
            float2 q1 = *(const float2*)(bqrow + (kb + 8) * 4);
            uint32_t ah[4], al[4];
            {
                float2 d = *(const float2*)(bd_lo + kb * 4);
                split_pack(fmaxf(d.x + q0.x, 0.0f), fmaxf(d.y + q0.y, 0.0f), ah[0], al[0]);
            }
            {
                float2 d = *(const float2*)(bd_hi + kb * 4);
                split_pack(fmaxf(d.x + q0.x, 0.0f), fmaxf(d.y + q0.y, 0.0f), ah[1], al[1]);
            }
            {
                float2 d = *(const float2*)(bd_lo + (kb + 8) * 4);
                split_pack(fmaxf(d.x + q1.x, 0.0f), fmaxf(d.y + q1.y, 0.0f), ah[2], al[2]);
            }
            {
                float2 d = *(const float2*)(bd_hi + (kb + 8) * 4);
                split_pack(fmaxf(d.x + q1.x, 0.0f), fmaxf(d.y + q1.y, 0.0f), ah[3], al[3]);
            }
            #pragma unroll
            for (int nt = 0; nt < 4; nt++) {
                const int roff = (nrow + nt * 8) * W3_STR + kb * 2;
                uint32_t bh0 = *(const uint32_t*)(smem + SM_W3H + roff);
                uint32_t bh1 = *(const uint32_t*)(smem + SM_W3H + roff + 16);
                uint32_t bl0 = *(const uint32_t*)(smem + SM_W3L + roff);
                uint32_t bl1 = *(const uint32_t*)(smem + SM_W3L + roff + 16);
                mma_bf16(c[nt], ah[0], ah[1], ah[2], ah[3], bh0, bh1);
                mma_bf16(c[nt], al[0], al[1], al[2], al[3], bh0, bh1);
                mma_bf16(c[nt], ah[0], ah[1], ah[2], ah[3], bl0, bl1);
            }
        }

        float* redb = (float*)(smem + SM_RED) + (il & 1) * 256;
        float s_lo = 0.0f, s_hi = 0.0f;
        #pragma unroll
        for (int nt = 0; nt < 4; nt++) {
            int n0 = warp_n * 32 + nt * 8 + (lane & 3) * 2;
            float b30 = b3s[n0], b31 = b3s[n0 + 1];
            float w40 = w4s[n0], w41 = w4s[n0 + 1];
            s_lo += fmaxf(c[nt][0] + b30, 0.0f) * w40 + fmaxf(c[nt][1] + b31, 0.0f) * w41;
            s_hi += fmaxf(c[nt][2] + b30, 0.0f) * w40 + fmaxf(c[nt][3] + b31, 0.0f) * w41;
        }
        s_lo += __shfl_xor_sync(0xFFFFFFFFu, s_lo, 1);
        s_lo += __shfl_xor_sync(0xFFFFFFFFu, s_lo, 2);
        s_hi += __shfl_xor_sync(0xFFFFFFFFu, s_hi, 1);
        s_hi += __shfl_xor_sync(0xFFFFFFFFu, s_hi, 2);
        if ((lane & 3) == 0) {
            redb[r_lo * 4 + warp_n] = s_lo;
            redb[(r_lo + 8) * 4 + warp_n] = s_hi;
        }
        __syncthreads();
        if (t < 64) {
            float v = redb[t * 4] + redb[t * 4 + 1] + redb[t * 4 + 2] + redb[t * 4 + 3] + b4v;
            v = v > 0.0f ? v : 0.0f;
            pred[(size_t)(i0 + il) * ND + j0 + t] = v;
        }
    }
}

// ---------------- host orchestration ----------------
extern "C" void kernel_launch(void* const* d_in, const int* in_sizes, int n_in,
                              void* d_out, int out_size)
{
    const float* qfeat = (const float*)d_in[0];
    const float* dfeat = (const float*)d_in[1];
    const int*   qe    = (const int*)d_in[2];
    const int*   de    = (const int*)d_in[3];
    const int*   qi    = (const int*)d_in[4];
    const int*   di    = (const int*)d_in[5];
    const float* q_w0 = (const float*)d_in[6];
    const float* q_b0 = (const float*)d_in[7];
    const float* q_w1 = (const float*)d_in[8];
    const float* q_b1 = (const float*)d_in[9];
    const float* d_w0 = (const float*)d_in[10];
    const float* d_b0 = (const float*)d_in[11];
    const float* d_w1 = (const float*)d_in[12];
    const float* d_b1 = (const float*)d_in[13];
    const float* w1 = (const float*)d_in[14];
    const float* b1 = (const float*)d_in[15];
    const float* w2 = (const float*)d_in[16];
    const float* b2 = (const float*)d_in[17];
    const float* w3 = (const float*)d_in[18];
    const float* b3 = (const float*)d_in[19];
    const float* w4 = (const float*)d_in[20];
    const float* b4 = (const float*)d_in[21];

    const int EQ = in_sizes[2] / 2;
    const int ED = in_sizes[3] / 2;
    const int EM = in_sizes[4];

    float *qh, *dh, *qB, *dB, *cosw, *Bqp, *Bdp;
    __nv_bfloat16 *wh, *wl;
    cudaGetSymbolAddress((void**)&qh, g_qh);
    cudaGetSymbolAddress((void**)&dh, g_dh);
    cudaGetSymbolAddress((void**)&qB, g_qB);
    cudaGetSymbolAddress((void**)&dB, g_dB);
    cudaGetSymbolAddress((void**)&cosw, g_cosw);
    cudaGetSymbolAddress((void**)&Bqp, g_Bq);
    cudaGetSymbolAddress((void**)&Bdp, g_Bd);
    cudaGetSymbolAddress((void**)&wh, g_wh);
    cudaGetSymbolAddress((void**)&wl, g_wl);

    float* out = (float*)d_out;
    float* qOut = out + NQ * ND;
    float* dOut = qOut + NQ * CAT;

    cudaFuncSetAttribute(hgemm_kernel, cudaFuncAttributeMaxDynamicSharedMemorySize, HG_SMEM);
    cudaFuncSetAttribute(pair_hmma_kernel, cudaFuncAttributeMaxDynamicSharedMemorySize,
                         SM_PAIR_TOTAL);

    // ---- 1. pack all weights ----
    PackArgs pa;
    pa.j[0] = { q_w0,               DD,  DD,  DD,  OFF_QW0 };
    pa.j[1] = { d_w0,               DD,  DD,  DD,  OFF_DW0 };
    pa.j[2] = { q_w1,               CAT, DD,  DD,  OFF_QW1 };
    pa.j[3] = { d_w1,               CAT, DD,  DD,  OFF_DW1 };
    pa.j[4] = { w1,                 CAT, CAT, CAT, OFF_W1T };
    pa.j[5] = { w1 + CAT * CAT,     CAT, CAT, CAT, OFF_W1B };
    pa.j[6] = { w2,                 CAT, DD,  DD,  OFF_W2  };
    pa.j[7] = { w3,                 DD,  128, 128, OFF_W3  };
    pack_kernel<<<dim3(256, 8), 256>>>(pa, wh, wl);

    // ---- 2. CSR build ----
    const int totE = EQ + ED + 2 * EM;
    csr_zero_kernel<<<4, 256>>>();
    csr_count_kernel<<<(totE + 255) / 256, 256>>>(qe + EQ, EQ, de + ED, ED, qi, di, EM);
    csr_scan_kernel<<<4, 1024>>>();
    csr_fill_kernel<<<(totE + 255) / 256, 256>>>(qe, qe + EQ, EQ, de, de + ED, ED, qi, di, EM);

    const int nodeBlocks = (NQ + ND) * 64 / 256;

    // ---- 3. layer 0 ----
    {
        GemmJob jq = { qfeat, wh + OFF_QW0, wl + OFF_QW0, qh, nullptr, NQ, DD, DD, DD, DD };
        GemmJob jd = { dfeat, wh + OFF_DW0, wl + OFF_DW0, dh, nullptr, ND, DD, DD, DD, DD };
        hgemm_kernel<<<dim3(DD / 64, ND / 64, 2), 256, HG_SMEM>>>(jq, jd);
    }
    gcn_gather_kernel<<<nodeBlocks, 256>>>(qh, dh, q_b0, d_b0, qB, dB);
    cos_norm_kernel<<<(EM + 7) / 8, 256>>>(qi, di, EM, qB, dB, cosw);
    softmax_kernel<<<1, 1024>>>(cosw, EM);
    cross_gather_kernel<<<nodeBlocks, 256>>>(qB, dB, cosw);

    // ---- 4. layer 1 (outputs straight into d_out) ----
    {
        GemmJob jq = { qB, wh + OFF_QW1, wl + OFF_QW1, qh, nullptr, NQ, DD, CAT, CAT, DD };
        GemmJob jd = { dB, wh + OFF_DW1, wl + OFF_DW1, dh, nullptr, ND, DD, CAT, CAT, DD };
        hgemm_kernel<<<dim3(DD / 64, ND / 64, 2), 256, HG_SMEM>>>(jq, jd);
    }
    gcn_gather_kernel<<<nodeBlocks, 256>>>(qh, dh, q_b1, d_b1, qOut, dOut);
    cos_norm_kernel<<<(EM + 7) / 8, 256>>>(qi, di, EM, qOut, dOut, cosw);
    softmax_kernel<<<1, 1024>>>(cosw, EM);
    cross_gather_kernel<<<nodeBlocks, 256>>>(qOut, dOut, cosw);

    // ---- 5. final scoring (w1/w2 folded) ----
    {
        GemmJob jq = { qOut, wh + OFF_W1T, wl + OFF_W1T, qB, b1, NQ, CAT, CAT, CAT, CAT };
        GemmJob jd = { dOut, wh + OFF_W1B, wl + OFF_W1B, dB, nullptr, ND, CAT, CAT, CAT, CAT };
        hgemm_kernel<<<dim3(CAT / 64, ND / 64, 2), 256, HG_SMEM>>>(jq, jd);
    }
    {
        GemmJob jq = { qB, wh + OFF_W2, wl + OFF_W2, Bqp, b2, NQ, DD, CAT, CAT, DD };
        GemmJob jd = { dB, wh + OFF_W2, wl + OFF_W2, Bdp, nullptr, ND, DD, CAT, CAT, DD };
        hgemm_kernel<<<dim3(DD / 64, ND / 64, 2), 256, HG_SMEM>>>(jq, jd);
    }

    // ---- 6. pair MLP -> pred ----
    dim3 pg(ND / 64, NQ / 8);
    pair_hmma_kernel<<<pg, 512, SM_PAIR_TOTAL>>>(Bqp, Bdp, wh + OFF_W3, wl + OFF_W3,
                                                 b3, w4, b4, out);
}

// round 16
// speedup vs baseline: 1.2576x; 1.0152x over previous
#include <cuda_runtime.h>
#include <cuda_bf16.h>
#include <cstdint>
#include <math.h>

#define NQ 128
#define ND 1024
#define DD 256
#define CAT 512
#define EQMAX 2048
#define EDMAX 32768
#define EMMAX 8192

// ---------------- device scratch ----------------
__device__ float g_qh[NQ * DD];
__device__ float g_dh[ND * DD];
__device__ float g_qB[NQ * CAT];
__device__ float g_dB[ND * CAT];
__device__ float g_cosw[EMMAX];
__device__ float g_Bq[NQ * DD];
__device__ float g_Bd[ND * DD];

// CSR structures (static graphs -> built once per run)
__device__ int   g_qcnt[NQ],  g_qoff[NQ + 1],  g_qsrcs[EQMAX];
__device__ float g_qcoef[EQMAX];
__device__ int   g_dcnt[ND],  g_doff[ND + 1],  g_dsrcs[EDMAX];
__device__ float g_dcoef[EDMAX];
__device__ int   g_mqcnt[NQ], g_mqoff[NQ + 1];
__device__ int2  g_mql[EMMAX];            // (edge, d-node)
__device__ int   g_mdcnt[ND], g_mdoff[ND + 1];
__device__ int2  g_mdl[EMMAX];            // (edge, q-node)

// packed weights: [N][K] bf16, hi and lo parts
#define OFF_QW0 0
#define OFF_DW0 65536
#define OFF_QW1 131072
#define OFF_DW1 262144
#define OFF_W1T 393216
#define OFF_W1B 655360
#define OFF_W2  917504
#define OFF_W3  1048576
#define WPACK_TOTAL 1081344
__device__ __align__(16) __nv_bfloat16 g_wh[WPACK_TOTAL];
__device__ __align__(16) __nv_bfloat16 g_wl[WPACK_TOTAL];

// ---------------- shared helpers ----------------
__device__ __forceinline__ void mma_bf16(float c[4],
                                         uint32_t a0, uint32_t a1, uint32_t a2, uint32_t a3,
                                         uint32_t b0, uint32_t b1)
{
    asm volatile("mma.sync.aligned.m16n8k16.row.col.f32.bf16.bf16.f32 "
                 "{%0,%1,%2,%3}, {%4,%5,%6,%7}, {%8,%9}, {%0,%1,%2,%3};"
                 : "+f"(c[0]), "+f"(c[1]), "+f"(c[2]), "+f"(c[3])
                 : "r"(a0), "r"(a1), "r"(a2), "r"(a3), "r"(b0), "r"(b1));
}

__device__ __forceinline__ void split_pack(float v0, float v1, uint32_t& hi, uint32_t& lo)
{
    asm("cvt.rn.bf16x2.f32 %0, %1, %2;" : "=r"(hi) : "f"(v1), "f"(v0));
    float h0 = __uint_as_float(hi << 16);
    float h1 = __uint_as_float(hi & 0xffff0000u);
    float r0 = v0 - h0, r1 = v1 - h1;
    asm("cvt.rn.bf16x2.f32 %0, %1, %2;" : "=r"(lo) : "f"(r1), "f"(r0));
}

// ---------------- weight pack: transpose + bf16 split ----------------
struct PackJob { const float* src; int K, N, ld; int64_t off; };
struct PackArgs { PackJob j[8]; };

__global__ void pack_kernel(PackArgs pa, __nv_bfloat16* __restrict__ wh,
                            __nv_bfloat16* __restrict__ wl)
{
    __shared__ float tile[32][33];
    const PackJob jb = pa.j[blockIdx.y];
    int ntilesK = jb.K >> 5;
    int ntiles = ntilesK * (jb.N >> 5);
    if ((int)blockIdx.x >= ntiles) return;
    int kt = blockIdx.x % ntilesK, nt = blockIdx.x / ntilesK;
    int tx = threadIdx.x & 31, ty = threadIdx.x >> 5;
    #pragma unroll
    for (int p = 0; p < 4; p++) {
        int row = ty + p * 8;
        tile[row][tx] = jb.src[(size_t)(kt * 32 + row) * jb.ld + nt * 32 + tx];
    }
    __syncthreads();
    #pragma unroll
    for (int p = 0; p < 4; p++) {
        int row = ty + p * 8;
        float v = tile[tx][row];
        __nv_bfloat16 h = __float2bfloat16(v);
        float r = v - __bfloat162float(h);
        size_t o = jb.off + (size_t)(nt * 32 + row) * jb.K + kt * 32 + tx;
        wh[o] = h;
        wl[o] = __float2bfloat16(r);
    }
}

// ---------------- CSR build (R12 4-kernel chain, unchanged) ----------------
__global__ void csr_zero_kernel()
{
    int i = blockIdx.x * blockDim.x + threadIdx.x;
    if (i < NQ) { g_qcnt[i] = 0; g_mqcnt[i] = 0; }
    if (i < ND) { g_dcnt[i] = 0; g_mdcnt[i] = 0; }
}

__global__ void csr_count_kernel(const int* __restrict__ qdst, int EQ,
                                 const int* __restrict__ ddst, int ED,
                                 const int* __restrict__ qi, const int* __restrict__ di, int EM)
{
    int e = blockIdx.x * blockDim.x + threadIdx.x;
    if (e < EQ) atomicAdd(&g_qcnt[qdst[e]], 1);
    else if (e < EQ + ED) atomicAdd(&g_dcnt[ddst[e - EQ]], 1);
    else if (e < EQ + ED + EM) atomicAdd(&g_mqcnt[qi[e - EQ - ED]], 1);
    else if (e < EQ + ED + 2 * EM) atomicAdd(&g_mdcnt[di[e - EQ - ED - EM]], 1);
}

__global__ void __launch_bounds__(1024) csr_scan_kernel()
{
    __shared__ int s[1024];
    int* cnt; int* off; int n;
    switch (blockIdx.x) {
        case 0: cnt = g_qcnt;  off = g_qoff;  n = NQ; break;
        case 1: cnt = g_dcnt;  off = g_doff;  n = ND; break;
        case 2: cnt = g_mqcnt; off = g_mqoff; n = NQ; break;
        default: cnt = g_mdcnt; off = g_mdoff; n = ND; break;
    }
    int t = threadIdx.x;
    s[t] = (t < n) ? cnt[t] : 0;
    __syncthreads();
    for (int o = 1; o < 1024; o <<= 1) {
        int v = (t >= o) ? s[t - o] : 0;
        __syncthreads();
        s[t] += v;
        __syncthreads();
    }
    if (t < n) {
        off[t + 1] = s[t];
        if (t == 0) off[0] = 0;
        cnt[t] = 0;
    }
}

__global__ void csr_fill_kernel(const int* __restrict__ qsrc, const int* __restrict__ qdst, int EQ,
                                const int* __restrict__ dsrc, const int* __restrict__ ddst, int ED,
                                const int* __restrict__ qi, const int* __restrict__ di, int EM)
{
    int e = blockIdx.x * blockDim.x + threadIdx.x;
    if (e < EQ) {
        int s = qsrc[e], d = qdst[e];
        int p = g_qoff[d] + atomicAdd(&g_qcnt[d], 1);
        g_qsrcs[p] = s;
        float degs = (float)(g_qoff[s + 1] - g_qoff[s]) + 1.0f;
        float degd = (float)(g_qoff[d + 1] - g_qoff[d]) + 1.0f;
        g_qcoef[p] = rsqrtf(degs) * rsqrtf(degd);
    } else if (e < EQ + ED) {
        int w = e - EQ;
        int s = dsrc[w], d = ddst[w];
        int p = g_doff[d] + atomicAdd(&g_dcnt[d], 1);
        g_dsrcs[p] = s;
        float degs = (float)(g_doff[s + 1] - g_doff[s]) + 1.0f;
        float degd = (float)(g_doff[d + 1] - g_doff[d]) + 1.0f;
        g_dcoef[p] = rsqrtf(degs) * rsqrtf(degd);
    } else if (e < EQ + ED + EM) {
        int w = e - EQ - ED;
        int q = qi[w];
        int p = g_mqoff[q] + atomicAdd(&g_mqcnt[q], 1);
        g_mql[p] = make_int2(w, di[w]);
    } else if (e < EQ + ED + 2 * EM) {
        int w = e - EQ - ED - EM;
        int d = di[w];
        int p = g_mdoff[d] + atomicAdd(&g_mdcnt[d], 1);
        g_mdl[p] = make_int2(w, qi[w]);
    }
}

// ---------------- HMMA split-bf16 GEMM, 64x64 tiles (R6/R7, unchanged) ----------------
struct GemmJob {
    const float* A;
    const __nv_bfloat16* Bh;
    const __nv_bfloat16* Bl;
    float* C;
    const float* bias;
    int M, N, K, lda, ldc;
};

#define HG_A    0
#define HG_ASTR 288
#define HG_BH   18432
#define HG_BL   27648
#define HG_BSTR 144
#define HG_SMEM 36864

__global__ void __launch_bounds__(256, 2)
hgemm_kernel(GemmJob j0, GemmJob j1)
{
    GemmJob jb = (blockIdx.z == 0) ? j0 : j1;
    const int n0 = blockIdx.x * 64;
    const int m0 = blockIdx.y * 64;
    if (n0 >= jb.N || m0 >= jb.M) return;
    extern __shared__ char sm[];
    const int t = threadIdx.x, lane = t & 31, wid = t >> 5;
    const int warp_m = wid & 1, warp_n = wid >> 1;
    const int qr = lane >> 2, qk = (lane & 3) * 2;
    float acc[2][2][4] = {};

    for (int kc = 0; kc < jb.K; kc += 64) {
        __syncthreads();
        {
            int row = t >> 2, c4 = (t & 3) * 4;
            const float4* src = (const float4*)(jb.A + (size_t)(m0 + row) * jb.lda + kc) + c4;
            float4* dst = (float4*)(sm + HG_A + row * HG_ASTR + c4 * 16);
            #pragma unroll
            for (int i = 0; i < 4; i++) dst[i] = src[i];
        }
        #pragma unroll
        for (int p = 0; p < 2; p++) {
            int idx = t + p * 256;
            int row = idx >> 3, c = idx & 7;
            size_t go = (size_t)(n0 + row) * jb.K + kc + c * 8;
            *(uint4*)(sm + HG_BH + row * HG_BSTR + c * 16) = *(const uint4*)(jb.Bh + go);
            *(uint4*)(sm + HG_BL + row * HG_BSTR + c * 16) = *(const uint4*)(jb.Bl + go);
        }
        __syncthreads();
        #pragma unroll
        for (int kk = 0; kk < 64; kk += 16) {
            uint32_t bh[2][2], bl[2][2];
            #pragma unroll
            for (int f = 0; f < 2; f++) {
                int n = warp_n * 16 + f * 8 + qr;
                const char* bp = sm + n * HG_BSTR + (kk + qk) * 2;
                bh[f][0] = *(const uint32_t*)(bp + HG_BH);
                bh[f][1] = *(const uint32_t*)(bp + HG_BH + 16);
                bl[f][0] = *(const uint32_t*)(bp + HG_BL);
                bl[f][1] = *(const uint32_t*)(bp + HG_BL + 16);
            }
            #pragma unroll
            for (int s = 0; s < 2; s++) {
                int r = warp_m * 32 + s * 16 + qr;
                const char* ap = sm + HG_A + r * HG_ASTR + (kk + qk) * 4;
                float2 a0 = *(const float2*)ap;
                float2 a1 = *(const float2*)(ap + 8 * HG_ASTR);
                float2 a2 = *(const float2*)(ap + 32);
                float2 a3 = *(const float2*)(ap + 8 * HG_ASTR + 32);
                uint32_t ah[4], al[4];
                split_pack(a0.x, a0.y, ah[0], al[0]);
                split_pack(a1.x, a1.y, ah[1], al[1]);
                split_pack(a2.x, a2.y, ah[2], al[2]);
                split_pack(a3.x, a3.y, ah[3], al[3]);
                #pragma unroll
                for (int f = 0; f < 2; f++) {
                    mma_bf16(acc[s][f], ah[0], ah[1], ah[2], ah[3], bh[f][0], bh[f][1]);
                    mma_bf16(acc[s][f], al[0], al[1], al[2], al[3], bh[f][0], bh[f][1]);
                    mma_bf16(acc[s][f], ah[0], ah[1], ah[2], ah[3], bl[f][0], bl[f][1]);
                }
            }
        }
    }
    #pragma unroll
    for (int s = 0; s < 2; s++) {
        int r = m0 + warp_m * 32 + s * 16 + qr;
        #pragma unroll
        for (int f = 0; f < 2; f++) {
            int n = n0 + warp_n * 16 + f * 8 + qk;
            float bs0 = jb.bias ? jb.bias[n] : 0.0f;
            float bs1 = jb.bias ? jb.bias[n + 1] : 0.0f;
            float2 v0 = { acc[s][f][0] + bs0, acc[s][f][1] + bs1 };
            float2 v1 = { acc[s][f][2] + bs0, acc[s][f][3] + bs1 };
            *(float2*)(jb.C + (size_t)r * jb.ldc + n) = v0;
            *(float2*)(jb.C + (size_t)(r + 8) * jb.ldc + n) = v1;
        }
    }
}

// ---------------- GCN gather (R14, unchanged) ----------------
__global__ void gcn_gather_kernel(const float* __restrict__ qh, const float* __restrict__ dh,
                                  const float* __restrict__ qb, const float* __restrict__ db,
                                  float* __restrict__ qout, float* __restrict__ dout)
{
    const float4 z4 = {0.f, 0.f, 0.f, 0.f};
    int v = blockIdx.x * blockDim.x + threadIdx.x;
    const float* h; const float* b; float* out;
    const int* off; const int* srcs; const float* coefs; int node;
    if (v < NQ * 64) {
        node = v >> 6; h = qh; b = qb; out = qout;
        off = g_qoff; srcs = g_qsrcs; coefs = g_qcoef;
    } else if (v < (NQ + ND) * 64) {
        v -= NQ * 64;
        node = v >> 6; h = dh; b = db; out = dout;
        off = g_doff; srcs = g_dsrcs; coefs = g_dcoef;
    } else return;
    int c = v & 63;
    int lo = off[node], hi = off[node + 1];
    float invd = 1.0f / ((float)(hi - lo) + 1.0f);
    float4 hh = ((const float4*)h)[node * 64 + c];
    float4 bb = ((const float4*)b)[c];
    float4 acc0 = { hh.x * invd + bb.x, hh.y * invd + bb.y,
                    hh.z * invd + bb.z, hh.w * invd + bb.w };
    float4 acc1 = z4, acc2 = z4, acc3 = z4;
    int k = lo;
    for (; k + 4 <= hi; k += 4) {
        int s0 = srcs[k], s1 = srcs[k + 1], s2 = srcs[k + 2], s3 = srcs[k + 3];
        float c0 = coefs[k], c1 = coefs[k + 1], c2 = coefs[k + 2], c3 = coefs[k + 3];
        float4 h0 = ((const float4*)h)[s0 * 64 + c];
        float4 h1 = ((const float4*)h)[s1 * 64 + c];
        float4 h2 = ((const float4*)h)[s2 * 64 + c];
        float4 h3 = ((const float4*)h)[s3 * 64 + c];
        acc0.x += c0 * h0.x; acc0.y += c0 * h0.y; acc0.z += c0 * h0.z; acc0.w += c0 * h0.w;
        acc1.x += c1 * h1.x; acc1.y += c1 * h1.y; acc1.z += c1 * h1.z; acc1.w += c1 * h1.w;
        acc2.x += c2 * h2.x; acc2.y += c2 * h2.y; acc2.z += c2 * h2.z; acc2.w += c2 * h2.w;
        acc3.x += c3 * h3.x; acc3.y += c3 * h3.y; acc3.z += c3 * h3.z; acc3.w += c3 * h3.w;
    }
    for (; k < hi; k++) {
        int s0 = srcs[k];
        float c0 = coefs[k];
        float4 h0 = ((const float4*)h)[s0 * 64 + c];
        acc0.x += c0 * h0.x; acc0.y += c0 * h0.y; acc0.z += c0 * h0.z; acc0.w += c0 * h0.w;
    }
    acc0.x = fmaxf(acc0.x + acc1.x + acc2.x + acc3.x, 0.f);
    acc0.y = fmaxf(acc0.y + acc1.y + acc2.y + acc3.y, 0.f);
    acc0.z = fmaxf(acc0.z + acc1.z + acc2.z + acc3.z, 0.f);
    acc0.w = fmaxf(acc0.w + acc1.w + acc2.w + acc3.w, 0.f);
    ((float4*)out)[node * 128 + c] = acc0;
    ((float4*)out)[node * 128 + 64 + c] = z4;
}

// ---------------- cross-matching kernels (R12, unchanged) ----------------
__global__ void cos_norm_kernel(const int* __restrict__ qi, const int* __restrict__ di, int E,
                                const float* __restrict__ qbuf, const float* __restrict__ dbuf,
                                float* __restrict__ cosw)
{
    int e = blockIdx.x * (blockDim.x >> 5) + (threadIdx.x >> 5);
    int lane = threadIdx.x & 31;
    if (e >= E) return;
    const float* qp = qbuf + qi[e] * CAT;
    const float* dp = dbuf + di[e] * CAT;
    float qq = 0.f, dd = 0.f, qd = 0.f;
    for (int k = lane; k < DD; k += 32) {
        float a = qp[k], b = dp[k];
        qq += a * a; dd += b * b; qd += a * b;
    }
    #pragma unroll
    for (int o = 16; o; o >>= 1) {
        qq += __shfl_xor_sync(0xFFFFFFFFu, qq, o);
        dd += __shfl_xor_sync(0xFFFFFFFFu, dd, o);
        qd += __shfl_xor_sync(0xFFFFFFFFu, qd, o);
    }
    if (lane == 0)
        cosw[e] = qd / (fmaxf(sqrtf(qq), 1e-8f) * fmaxf(sqrtf(dd), 1e-8f));
}

__global__ void softmax_kernel(float* __restrict__ cosw, int E)
{
    __shared__ float red[1024];
    int t = threadIdx.x;
    float m = -1e30f;
    for (int e = t; e < E; e += 1024) m = fmaxf(m, cosw[e]);
    red[t] = m; __syncthreads();
    for (int s = 512; s; s >>= 1) { if (t < s) red[t] = fmaxf(red[t], red[t + s]); __syncthreads(); }
    float mx = red[0]; __syncthreads();
    float sum = 0.f;
    for (int e = t; e < E; e += 1024) sum += expf(cosw[e] - mx);
    red[t] = sum; __syncthreads();
    for (int s = 512; s; s >>= 1) { if (t < s) red[t] += red[t + s]; __syncthreads(); }
    float inv = 1.0f / red[0];
    for (int e = t; e < E; e += 1024) cosw[e] = expf(cosw[e] - mx) * inv;
}

__global__ void cross_gather_kernel(float* __restrict__ qbuf, float* __restrict__ dbuf,
                                    const float* __restrict__ w)
{
    const float4 z4 = {0.f, 0.f, 0.f, 0.f};
    int v = blockIdx.x * blockDim.x + threadIdx.x;
    const float* rd; float* wrbuf; const int* off; const int2* list; int node;
    if (v < NQ * 64) {
        node = v >> 6; rd = dbuf; wrbuf = qbuf; off = g_mqoff; list = g_mql;
    } else if (v < (NQ + ND) * 64) {
        v -= NQ * 64;
        node = v >> 6; rd = qbuf; wrbuf = dbuf; off = g_mdoff; list = g_mdl;
    } else return;
    int c = v & 63;
    int lo = off[node], hi = off[node + 1];
    float4 acc0 = z4, acc1 = z4;
    int k = lo;
    for (; k + 2 <= hi; k += 2) {
        int2 p0 = list[k], p1 = list[k + 1];
        float w0 = w[p0.x], w1 = w[p1.x];
        float4 v0 = ((const float4*)rd)[p0.y * 128 + c];
        float4 v1 = ((const float4*)rd)[p1.y * 128 + c];
        acc0.x += w0 * v0.x; acc0.y += w0 * v0.y;
        acc0.z += w0 * v0.z; acc0.w += w0 * v0.w;
        acc1.x += w1 * v1.x; acc1.y += w1 * v1.y;
        acc1.z += w1 * v1.z; acc1.w += w1 * v1.w;
    }
    if (k < hi) {
        int2 p0 = list[k];
        float w0 = w[p0.x];
        float4 v0 = ((const float4*)rd)[p0.y * 128 + c];
        acc0.x += w0 * v0.x; acc0.y += w0 * v0.y;
        acc0.z += w0 * v0.z; acc0.w += w0 * v0.w;
    }
    acc0.x += acc1.x; acc0.y += acc1.y; acc0.z += acc1.z; acc0.w += acc1.w;
    ((float4*)wrbuf)[node * 128 + 64 + c] = acc0;
}

// ---------------- HMMA pair-MLP: 16-i groups, one wave (128 CTAs) ----------------
#define SM_BQ   0
#define SM_B3   16384
#define SM_W4   16896
#define SM_RED  17408
#define SM_BD   19456
#define BD_STR  1032
#define SM_W3H  (SM_BD + 64 * BD_STR)           // 85504
#define W3_STR  528
#define SM_W3L  (SM_W3H + 128 * W3_STR)         // 153088
#define SM_PAIR_TOTAL (SM_W3L + 128 * W3_STR)   // 220672

__global__ void __launch_bounds__(512, 1)
pair_hmma_kernel(const float* __restrict__ Bq, const float* __restrict__ Bd,
                 const __nv_bfloat16* __restrict__ w3hi, const __nv_bfloat16* __restrict__ w3lo,
                 const float* __restrict__ b3, const float* __restrict__ w4,
                 const float* __restrict__ b4, float* __restrict__ pred)
{
    extern __shared__ char smem[];
    const int t = threadIdx.x, lane = t & 31, wid = t >> 5;
    const int warp_m = wid & 3, warp_n = wid >> 2;
    const int j0 = blockIdx.x * 64;
    const int i0 = blockIdx.y * 16;

    // Bq block: 16 rows x 256 f32 = 1024 uint4, two per thread
    ((uint4*)(smem + SM_BQ))[t] = ((const uint4*)(Bq + (size_t)i0 * DD))[t];
    ((uint4*)(smem + SM_BQ))[t + 512] = ((const uint4*)(Bq + (size_t)i0 * DD))[t + 512];
    // Bd tile [64 x 256 f32], stride 1032B
    for (int v = t; v < 64 * 128; v += 512) {
        int row = v >> 7, c = v & 127;
        *(float2*)(smem + SM_BD + row * BD_STR + c * 8) =
            ((const float2*)(Bd + (size_t)(j0 + row) * DD))[c];
    }
    // w3 hi + lo [128 x 256 bf16], stride 528B
    for (int v = t; v < 128 * 32; v += 512) {
        int row = v >> 5, c = v & 31;
        *(uint4*)(smem + SM_W3H + row * W3_STR + c * 16) =
            ((const uint4*)(w3hi + (size_t)row * DD))[c];
        *(uint4*)(smem + SM_W3L + row * W3_STR + c * 16) =
            ((const uint4*)(w3lo + (size_t)row * DD))[c];
    }
    if (t < 32) ((uint4*)(smem + SM_B3))[t] = ((const uint4*)b3)[t];
    else if (t < 64) ((uint4*)(smem + SM_W4))[t - 32] = ((const uint4*)w4)[t - 32];
    const float b4v = b4[0];
    __syncthreads();

    const float* b3s = (const float*)(smem + SM_B3);
    const float* w4s = (const float*)(smem + SM_W4);

    const int r_lo = warp_m * 16 + (lane >> 2);
    const char* bd_lo = smem + SM_BD + r_lo * BD_STR;
    const char* bd_hi = bd_lo + 8 * BD_STR;
    const int kq = (lane & 3) * 2;
    const int nrow = warp_n * 32 + (lane >> 2);

    for (int il = 0; il < 16; il++) {
        const char* bqrow = smem + SM_BQ + il * 1024;
        float c[4][4];
        #pragma unroll
        for (int nt = 0; nt < 4; nt++)
            #pragma unroll
            for (int u = 0; u < 4; u++) c[nt][u] = 0.0f;

        #pragma unroll
        for (int ks = 0; ks < 16; ks++) {
            const int kb = ks * 16 + kq;
            float2 q0 = *(const float2*)(bqrow + kb * 4);
            float2 q1 = *(const float2*)(bqrow + (kb + 8) * 4);
            uint32_t ah[4], al[4];
            {
                float2 d = *(const float2*)(bd_lo + kb * 4);
                split_pack(fmaxf(d.x + q0.x, 0.0f), fmaxf(d.y + q0.y, 0.0f), ah[0], al[0]);
            }
            {
                float2 d = *(const float2*)(bd_hi + kb * 4);
                split_pack(fmaxf(d.x + q0.x, 0.0f), fmaxf(d.y + q0.y, 0.0f), ah[1], al[1]);
            }
            {
                float2 d = *(const float2*)(bd_lo + (kb + 8) * 4);
                split_pack(fmaxf(d.x + q1.x, 0.0f), fmaxf(d.y + q1.y, 0.0f), ah[2], al[2]);
            }
            {
                float2 d = *(const float2*)(bd_hi + (kb + 8) * 4);
                split_pack(fmaxf(d.x + q1.x, 0.0f), fmaxf(d.y + q1.y, 0.0f), ah[3], al[3]);
            }
            #pragma unroll
            for (int nt = 0; nt < 4; nt++) {
                const int roff = (nrow + nt * 8) * W3_STR + kb * 2;
                uint32_t bh0 = *(const uint32_t*)(smem + SM_W3H + roff);
                uint32_t bh1 = *(const uint32_t*)(smem + SM_W3H + roff + 16);
                uint32_t bl0 = *(const uint32_t*)(smem + SM_W3L + roff);
                uint32_t bl1 = *(const uint32_t*)(smem + SM_W3L + roff + 16);
                mma_bf16(c[nt], ah[0], ah[1], ah[2], ah[3], bh0, bh1);
                mma_bf16(c[nt], al[0], al[1], al[2], al[3], bh0, bh1);
                mma_bf16(c[nt], ah[0], ah[1], ah[2], ah[3], bl0, bl1);
            }
        }

        float* redb = (float*)(smem + SM_RED) + (il & 1) * 256;
        float s_lo = 0.0f, s_hi = 0.0f;
        #pragma unroll
        for (int nt = 0; nt < 4; nt++) {
            int n0 = warp_n * 32 + nt * 8 + (lane & 3) * 2;
            float b30 = b3s[n0], b31 = b3s[n0 + 1];
            float w40 = w4s[n0], w41 = w4s[n0 + 1];
            s_lo += fmaxf(c[nt][0] + b30, 0.0f) * w40 + fmaxf(c[nt][1] + b31, 0.0f) * w41;
            s_hi += fmaxf(c[nt][2] + b30, 0.0f) * w40 + fmaxf(c[nt][3] + b31, 0.0f) * w41;
        }
        s_lo += __shfl_xor_sync(0xFFFFFFFFu, s_lo, 1);
        s_lo += __shfl_xor_sync(0xFFFFFFFFu, s_lo, 2);
        s_hi += __shfl_xor_sync(0xFFFFFFFFu, s_hi, 1);
        s_hi += __shfl_xor_sync(0xFFFFFFFFu, s_hi, 2);
        if ((lane & 3) == 0) {
            redb[r_lo * 4 + warp_n] = s_lo;
            redb[(r_lo + 8) * 4 + warp_n] = s_hi;
        }
        __syncthreads();
        if (t < 64) {
            float v = redb[t * 4] + redb[t * 4 + 1] + redb[t * 4 + 2] + redb[t * 4 + 3] + b4v;
            v = v > 0.0f ? v : 0.0f;
            pred[(size_t)(i0 + il) * ND + j0 + t] = v;
        }
    }
}

// ---------------- host orchestration ----------------
extern "C" void kernel_launch(void* const* d_in, const int* in_sizes, int n_in,
                              void* d_out, int out_size)
{
    const float* qfeat = (const float*)d_in[0];
    const float* dfeat = (const float*)d_in[1];
    const int*   qe    = (const int*)d_in[2];
    const int*   de    = (const int*)d_in[3];
    const int*   qi    = (const int*)d_in[4];
    const int*   di    = (const int*)d_in[5];
    const float* q_w0 = (const float*)d_in[6];
    const float* q_b0 = (const float*)d_in[7];
    const float* q_w1 = (const float*)d_in[8];
    const float* q_b1 = (const float*)d_in[9];
    const float* d_w0 = (const float*)d_in[10];
    const float* d_b0 = (const float*)d_in[11];
    const float* d_w1 = (const float*)d_in[12];
    const float* d_b1 = (const float*)d_in[13];
    const float* w1 = (const float*)d_in[14];
    const float* b1 = (const float*)d_in[15];
    const float* w2 = (const float*)d_in[16];
    const float* b2 = (const float*)d_in[17];
    const float* w3 = (const float*)d_in[18];
    const float* b3 = (const float*)d_in[19];
    const float* w4 = (const float*)d_in[20];
    const float* b4 = (const float*)d_in[21];

    const int EQ = in_sizes[2] / 2;
    const int ED = in_sizes[3] / 2;
    const int EM = in_sizes[4];

    float *qh, *dh, *qB, *dB, *cosw, *Bqp, *Bdp;
    __nv_bfloat16 *wh, *wl;
    cudaGetSymbolAddress((void**)&qh, g_qh);
    cudaGetSymbolAddress((void**)&dh, g_dh);
    cudaGetSymbolAddress((void**)&qB, g_qB);
    cudaGetSymbolAddress((void**)&dB, g_dB);
    cudaGetSymbolAddress((void**)&cosw, g_cosw);
    cudaGetSymbolAddress((void**)&Bqp, g_Bq);
    cudaGetSymbolAddress((void**)&Bdp, g_Bd);
    cudaGetSymbolAddress((void**)&wh, g_wh);
    cudaGetSymbolAddress((void**)&wl, g_wl);

    float* out = (float*)d_out;
    float* qOut = out + NQ * ND;
    float* dOut = qOut + NQ * CAT;

    cudaFuncSetAttribute(hgemm_kernel, cudaFuncAttributeMaxDynamicSharedMemorySize, HG_SMEM);
    cudaFuncSetAttribute(pair_hmma_kernel, cudaFuncAttributeMaxDynamicSharedMemorySize,
                         SM_PAIR_TOTAL);

    // ---- 1. pack all weights ----
    PackArgs pa;
    pa.j[0] = { q_w0,               DD,  DD,  DD,  OFF_QW0 };
    pa.j[1] = { d_w0,               DD,  DD,  DD,  OFF_DW0 };
    pa.j[2] = { q_w1,               CAT, DD,  DD,  OFF_QW1 };
    pa.j[3] = { d_w1,               CAT, DD,  DD,  OFF_DW1 };
    pa.j[4] = { w1,                 CAT, CAT, CAT, OFF_W1T };
    pa.j[5] = { w1 + CAT * CAT,     CAT, CAT, CAT, OFF_W1B };
    pa.j[6] = { w2,                 CAT, DD,  DD,  OFF_W2  };
    pa.j[7] = { w3,                 DD,  128, 128, OFF_W3  };
    pack_kernel<<<dim3(256, 8), 256>>>(pa, wh, wl);

    // ---- 2. CSR build ----
    const int totE = EQ + ED + 2 * EM;
    csr_zero_kernel<<<4, 256>>>();
    csr_count_kernel<<<(totE + 255) / 256, 256>>>(qe + EQ, EQ, de + ED, ED, qi, di, EM);
    csr_scan_kernel<<<4, 1024>>>();
    csr_fill_kernel<<<(totE + 255) / 256, 256>>>(qe, qe + EQ, EQ, de, de + ED, ED, qi, di, EM);

    const int nodeBlocks = (NQ + ND) * 64 / 256;

    // ---- 3. layer 0 ----
    {
        GemmJob jq = { qfeat, wh + OFF_QW0, wl + OFF_QW0, qh, nullptr, NQ, DD, DD, DD, DD };
        GemmJob jd = { dfeat, wh + OFF_DW0, wl + OFF_DW0, dh, nullptr, ND, DD, DD, DD, DD };
        hgemm_kernel<<<dim3(DD / 64, ND / 64, 2), 256, HG_SMEM>>>(jq, jd);
    }
    gcn_gather_kernel<<<nodeBlocks, 256>>>(qh, dh, q_b0, d_b0, qB, dB);
    cos_norm_kernel<<<(EM + 7) / 8, 256>>>(qi, di, EM, qB, dB, cosw);
    softmax_kernel<<<1, 1024>>>(cosw, EM);
    cross_gather_kernel<<<nodeBlocks, 256>>>(qB, dB, cosw);

    // ---- 4. layer 1 (outputs straight into d_out) ----
    {
        GemmJob jq = { qB, wh + OFF_QW1, wl + OFF_QW1, qh, nullptr, NQ, DD, CAT, CAT, DD };
        GemmJob jd = { dB, wh + OFF_DW1, wl + OFF_DW1, dh, nullptr, ND, DD, CAT, CAT, DD };
        hgemm_kernel<<<dim3(DD / 64, ND / 64, 2), 256, HG_SMEM>>>(jq, jd);
    }
    gcn_gather_kernel<<<nodeBlocks, 256>>>(qh, dh, q_b1, d_b1, qOut, dOut);
    cos_norm_kernel<<<(EM + 7) / 8, 256>>>(qi, di, EM, qOut, dOut, cosw);
    softmax_kernel<<<1, 1024>>>(cosw, EM);
    cross_gather_kernel<<<nodeBlocks, 256>>>(qOut, dOut, cosw);

    // ---- 5. final scoring (w1/w2 folded) ----
    {
        GemmJob jq = { qOut, wh + OFF_W1T, wl + OFF_W1T, qB, b1, NQ, CAT, CAT, CAT, CAT };
        GemmJob jd = { dOut, wh + OFF_W1B, wl + OFF_W1B, dB, nullptr, ND, CAT, CAT, CAT, CAT };
        hgemm_kernel<<<dim3(CAT / 64, ND / 64, 2), 256, HG_SMEM>>>(jq, jd);
    }
    {
        GemmJob jq = { qB, wh + OFF_W2, wl + OFF_W2, Bqp, b2, NQ, DD, CAT, CAT, DD };
        GemmJob jd = { dB, wh + OFF_W2, wl + OFF_W2, Bdp, nullptr, ND, DD, CAT, CAT, DD };
        hgemm_kernel<<<dim3(DD / 64, ND / 64, 2), 256, HG_SMEM>>>(jq, jd);
    }

    // ---- 6. pair MLP -> pred ----
    dim3 pg(ND / 64, NQ / 16);
    pair_hmma_kernel<<<pg, 512, SM_PAIR_TOTAL>>>(Bqp, Bdp, wh + OFF_W3, wl + OFF_W3,
                                                 b3, w4, b4, out);
}